// round 1
// baseline (speedup 1.0000x reference)
#include <cuda_runtime.h>
#include <cuda_fp16.h>
#include <cuda_bf16.h>
#include <mma.h>

using namespace nvcuda;

// Problem constants
#define T_TOK 2048
#define H_DIM 2048
#define I_DIM 1024
#define E_NUM 16
#define K_TOP 4
#define NPAIR (T_TOK * K_TOP)   // 8192 token-expert pairs total (exact)

// ---------------- static device scratch (allocation-free rule) ----------------
__device__ int    g_topk_idx[T_TOK * K_TOP];
__device__ float  g_topk_w[T_TOK * K_TOP];     // renormalized weights
__device__ int    g_counts[E_NUM];
__device__ int    g_off[E_NUM];
__device__ int    g_srcTok[NPAIR];             // pair row -> token id
__device__ float  g_pairw[NPAIR];              // pair row -> combine weight
__device__ int    g_rowOf[T_TOK * K_TOP];      // token,k -> pair row
__device__ __half g_act[(size_t)NPAIR * I_DIM];    // 16 MB, SwiGLU activations (fp16)
__device__ float  g_dout[(size_t)NPAIR * H_DIM];   // 64 MB, per-pair down-proj (fp32)

// ---------------- init ----------------
__global__ void init_kernel() {
    if (threadIdx.x < E_NUM) g_counts[threadIdx.x] = 0;
}

// ---------------- router: fp32 logits, top-4 on exp-scores, renorm ----------------
__global__ void router_kernel(const float* __restrict__ hidden,
                              const float* __restrict__ gate_w) {
    int t = blockIdx.x;
    __shared__ float sh[H_DIM];
    __shared__ float slog[E_NUM];
    int tid = threadIdx.x;                 // 128 threads
    for (int i = tid; i < H_DIM; i += 128) sh[i] = hidden[(size_t)t * H_DIM + i];
    __syncthreads();
    int wid = tid >> 5, lane = tid & 31;
    // each warp computes 4 experts
    for (int q = 0; q < 4; q++) {
        int e = wid * 4 + q;
        const float* g = gate_w + (size_t)e * H_DIM;
        float p = 0.f;
        for (int i = lane; i < H_DIM; i += 32) p += sh[i] * g[i];
        #pragma unroll
        for (int o = 16; o > 0; o >>= 1) p += __shfl_down_sync(0xffffffffu, p, o);
        if (lane == 0) slog[e] = p;
    }
    __syncthreads();
    if (tid == 0) {
        float mx = -1e30f;
        for (int e = 0; e < E_NUM; e++) mx = fmaxf(mx, slog[e]);
        float pr[E_NUM];
        for (int e = 0; e < E_NUM; e++) pr[e] = __expf(slog[e] - mx);
        // top-4 (softmax denominator cancels under renormalization)
        int   idx[K_TOP]; float w[K_TOP];
        for (int k = 0; k < K_TOP; k++) {
            float bv = -1.f; int bi = 0;
            for (int e = 0; e < E_NUM; e++) {
                bool used = false;
                for (int kk = 0; kk < k; kk++) if (idx[kk] == e) used = true;
                if (!used && pr[e] > bv) { bv = pr[e]; bi = e; }
            }
            idx[k] = bi; w[k] = bv;
        }
        float inv = 1.f / (w[0] + w[1] + w[2] + w[3]);
        for (int k = 0; k < K_TOP; k++) {
            g_topk_idx[t * K_TOP + k] = idx[k];
            g_topk_w[t * K_TOP + k]   = w[k] * inv;
            atomicAdd(&g_counts[idx[k]], 1);   // integer atomic: deterministic
        }
    }
}

// ---------------- offsets: exclusive prefix over 16 counts ----------------
__global__ void prefix_kernel() {
    if (threadIdx.x == 0) {
        int acc = 0;
        for (int e = 0; e < E_NUM; e++) { g_off[e] = acc; acc += g_counts[e]; }
    }
}

// ---------------- fill: deterministic ordered compaction per expert ----------------
__global__ void fill_kernel() {
    int e = blockIdx.x;
    int start = g_off[e];
    __shared__ int s_counter, s_prefix[8], s_wsum[8];
    int tid = threadIdx.x, lane = tid & 31, wid = tid >> 5;
    if (tid == 0) s_counter = 0;
    __syncthreads();
    for (int base = 0; base < T_TOK; base += 256) {
        int t = base + tid;
        int myk = -1;
        #pragma unroll
        for (int k = 0; k < K_TOP; k++) if (g_topk_idx[t * K_TOP + k] == e) myk = k;
        unsigned bal = __ballot_sync(0xffffffffu, myk >= 0);
        if (lane == 0) s_wsum[wid] = __popc(bal);
        __syncthreads();
        if (tid == 0) {
            int acc = s_counter;
            for (int w = 0; w < 8; w++) { s_prefix[w] = acc; acc += s_wsum[w]; }
            s_counter = acc;
        }
        __syncthreads();
        if (myk >= 0) {
            int j = s_prefix[wid] + __popc(bal & ((1u << lane) - 1));
            int r = start + j;
            g_srcTok[r] = t;
            g_pairw[r]  = g_topk_w[t * K_TOP + myk];
            g_rowOf[t * K_TOP + myk] = r;
        }
        __syncthreads();
    }
}

// ---------------- GEMM1: act = silu(X@W1) * (X@W3), per expert, fp16 wmma ----------------
// Block tile: BM=128, BN=64 (for both W1 and W3), BK=32. 256 threads = 8 warps (4x2 of 32x32).
__global__ __launch_bounds__(256) void gemm1_kernel(const float* __restrict__ hidden,
                                                    const float* __restrict__ w1,
                                                    const float* __restrict__ w3) {
    int e = blockIdx.z;
    int M_e = g_counts[e];
    int mbase = blockIdx.y * 128;
    if (mbase >= M_e) return;
    int n0 = blockIdx.x * 64;
    int rstart = g_off[e] + mbase;
    int mrem = M_e - mbase; if (mrem > 128) mrem = 128;

    __shared__ __align__(16) __half Ah[128][40];
    __shared__ __align__(16) __half B1h[32][72];
    __shared__ __align__(16) __half B3h[32][72];
    __shared__ __align__(16) float  stage[8][16][20];
    __shared__ int rows[128];

    int tid = threadIdx.x;
    if (tid < 128) rows[tid] = (tid < mrem) ? g_srcTok[rstart + tid] : 0;

    wmma::fragment<wmma::accumulator, 16, 16, 16, float> acc1[2][2], acc3[2][2];
    #pragma unroll
    for (int i = 0; i < 2; i++)
        #pragma unroll
        for (int j = 0; j < 2; j++) {
            wmma::fill_fragment(acc1[i][j], 0.f);
            wmma::fill_fragment(acc3[i][j], 0.f);
        }

    int wid = tid >> 5, lane = tid & 31;
    int wm = wid & 3, wn = wid >> 2;
    __syncthreads();

    for (int k0 = 0; k0 < H_DIM; k0 += 32) {
        // A tile: gathered hidden rows, fp32->fp16
        #pragma unroll
        for (int i = 0; i < 16; i++) {
            int idx = tid + i * 256; int m = idx >> 5; int k = idx & 31;
            float v = (m < mrem) ? hidden[(size_t)rows[m] * H_DIM + k0 + k] : 0.f;
            Ah[m][k] = __float2half(v);
        }
        // B tiles: w1/w3 [H, I] rows k0..k0+31, cols n0..n0+63
        #pragma unroll
        for (int i = 0; i < 8; i++) {
            int idx = tid + i * 256; int kb = idx >> 6; int n = idx & 63;
            size_t o = ((size_t)e * H_DIM + k0 + kb) * I_DIM + n0 + n;
            B1h[kb][n] = __float2half(w1[o]);
            B3h[kb][n] = __float2half(w3[o]);
        }
        __syncthreads();
        #pragma unroll
        for (int kk = 0; kk < 32; kk += 16) {
            wmma::fragment<wmma::matrix_a, 16, 16, 16, __half, wmma::row_major> af[2];
            wmma::load_matrix_sync(af[0], &Ah[wm * 32][kk], 40);
            wmma::load_matrix_sync(af[1], &Ah[wm * 32 + 16][kk], 40);
            wmma::fragment<wmma::matrix_b, 16, 16, 16, __half, wmma::row_major> bf1[2], bf3[2];
            #pragma unroll
            for (int j = 0; j < 2; j++) {
                wmma::load_matrix_sync(bf1[j], &B1h[kk][wn * 32 + j * 16], 72);
                wmma::load_matrix_sync(bf3[j], &B3h[kk][wn * 32 + j * 16], 72);
            }
            #pragma unroll
            for (int i = 0; i < 2; i++)
                #pragma unroll
                for (int j = 0; j < 2; j++) {
                    wmma::mma_sync(acc1[i][j], af[i], bf1[j], acc1[i][j]);
                    wmma::mma_sync(acc3[i][j], af[i], bf3[j], acc3[i][j]);
                }
        }
        __syncthreads();
    }

    // Epilogue: silu(h1)*h3 -> fp16 act (only valid rows)
    #pragma unroll
    for (int i = 0; i < 2; i++)
        #pragma unroll
        for (int j = 0; j < 2; j++) {
            #pragma unroll
            for (int x = 0; x < acc1[i][j].num_elements; x++) {
                float a = acc1[i][j].x[x];
                float sig = 1.0f / (1.0f + __expf(-a));
                acc1[i][j].x[x] = a * sig * acc3[i][j].x[x];
            }
            wmma::store_matrix_sync(&stage[wid][0][0], acc1[i][j], 20, wmma::mem_row_major);
            __syncwarp();
            for (int s2 = lane; s2 < 256; s2 += 32) {
                int rr = s2 >> 4, cc = s2 & 15;
                int m = wm * 32 + i * 16 + rr;
                if (m < mrem)
                    g_act[(size_t)(rstart + m) * I_DIM + n0 + wn * 32 + j * 16 + cc] =
                        __float2half(stage[wid][rr][cc]);
            }
            __syncwarp();
        }
}

// ---------------- GEMM2: dout = (act @ W2) * pairw, per expert ----------------
__global__ __launch_bounds__(256) void gemm2_kernel(const float* __restrict__ w2) {
    int e = blockIdx.z;
    int M_e = g_counts[e];
    int mbase = blockIdx.y * 128;
    if (mbase >= M_e) return;
    int n0 = blockIdx.x * 64;                  // over H
    int rstart = g_off[e] + mbase;
    int mrem = M_e - mbase; if (mrem > 128) mrem = 128;

    __shared__ __align__(16) __half Ah[128][40];
    __shared__ __align__(16) __half Bh[32][72];
    __shared__ __align__(16) float  stage[8][16][20];
    __shared__ float spw[128];

    int tid = threadIdx.x;
    if (tid < 128) spw[tid] = (tid < mrem) ? g_pairw[rstart + tid] : 0.f;

    wmma::fragment<wmma::accumulator, 16, 16, 16, float> acc[2][2];
    #pragma unroll
    for (int i = 0; i < 2; i++)
        #pragma unroll
        for (int j = 0; j < 2; j++) wmma::fill_fragment(acc[i][j], 0.f);

    int wid = tid >> 5, lane = tid & 31;
    int wm = wid & 3, wn = wid >> 2;
    __syncthreads();

    for (int k0 = 0; k0 < I_DIM; k0 += 32) {
        #pragma unroll
        for (int i = 0; i < 16; i++) {
            int idx = tid + i * 256; int m = idx >> 5; int k = idx & 31;
            Ah[m][k] = (m < mrem) ? g_act[(size_t)(rstart + m) * I_DIM + k0 + k]
                                  : __float2half(0.f);
        }
        #pragma unroll
        for (int i = 0; i < 8; i++) {
            int idx = tid + i * 256; int kb = idx >> 6; int n = idx & 63;
            Bh[kb][n] = __float2half(w2[((size_t)e * I_DIM + k0 + kb) * H_DIM + n0 + n]);
        }
        __syncthreads();
        #pragma unroll
        for (int kk = 0; kk < 32; kk += 16) {
            wmma::fragment<wmma::matrix_a, 16, 16, 16, __half, wmma::row_major> af[2];
            wmma::load_matrix_sync(af[0], &Ah[wm * 32][kk], 40);
            wmma::load_matrix_sync(af[1], &Ah[wm * 32 + 16][kk], 40);
            wmma::fragment<wmma::matrix_b, 16, 16, 16, __half, wmma::row_major> bf[2];
            #pragma unroll
            for (int j = 0; j < 2; j++)
                wmma::load_matrix_sync(bf[j], &Bh[kk][wn * 32 + j * 16], 72);
            #pragma unroll
            for (int i = 0; i < 2; i++)
                #pragma unroll
                for (int j = 0; j < 2; j++)
                    wmma::mma_sync(acc[i][j], af[i], bf[j], acc[i][j]);
        }
        __syncthreads();
    }

    #pragma unroll
    for (int i = 0; i < 2; i++)
        #pragma unroll
        for (int j = 0; j < 2; j++) {
            wmma::store_matrix_sync(&stage[wid][0][0], acc[i][j], 20, wmma::mem_row_major);
            __syncwarp();
            for (int s2 = lane; s2 < 256; s2 += 32) {
                int rr = s2 >> 4, cc = s2 & 15;
                int m = wm * 32 + i * 16 + rr;
                if (m < mrem)
                    g_dout[(size_t)(rstart + m) * H_DIM + n0 + wn * 32 + j * 16 + cc] =
                        stage[wid][rr][cc] * spw[m];
            }
            __syncwarp();
        }
}

// ---------------- combine: out[t] = sum_k dout[rowOf[t][k]] (deterministic) ----------------
__global__ void combine_kernel(float* __restrict__ out) {
    int t = blockIdx.x;
    int r0 = g_rowOf[t * K_TOP + 0];
    int r1 = g_rowOf[t * K_TOP + 1];
    int r2 = g_rowOf[t * K_TOP + 2];
    int r3 = g_rowOf[t * K_TOP + 3];
    const float4* d0 = (const float4*)(g_dout + (size_t)r0 * H_DIM);
    const float4* d1 = (const float4*)(g_dout + (size_t)r1 * H_DIM);
    const float4* d2 = (const float4*)(g_dout + (size_t)r2 * H_DIM);
    const float4* d3 = (const float4*)(g_dout + (size_t)r3 * H_DIM);
    float4* o = (float4*)(out + (size_t)t * H_DIM);
    for (int i = threadIdx.x; i < H_DIM / 4; i += 256) {
        float4 a = d0[i], b = d1[i], c = d2[i], d = d3[i];
        float4 r;
        r.x = a.x + b.x + c.x + d.x;
        r.y = a.y + b.y + c.y + d.y;
        r.z = a.z + b.z + c.z + d.z;
        r.w = a.w + b.w + c.w + d.w;
        o[i] = r;
    }
}

// ---------------- launch ----------------
extern "C" void kernel_launch(void* const* d_in, const int* in_sizes, int n_in,
                              void* d_out, int out_size) {
    const float* hidden = (const float*)d_in[0];
    const float* gate_w = (const float*)d_in[1];
    const float* w1     = (const float*)d_in[2];
    const float* w3     = (const float*)d_in[3];
    const float* w2     = (const float*)d_in[4];
    float* out = (float*)d_out;

    init_kernel<<<1, 32>>>();
    router_kernel<<<T_TOK, 128>>>(hidden, gate_w);
    prefix_kernel<<<1, 32>>>();
    fill_kernel<<<E_NUM, 256>>>();
    gemm1_kernel<<<dim3(I_DIM / 64, T_TOK / 128, E_NUM), 256>>>(hidden, w1, w3);
    gemm2_kernel<<<dim3(H_DIM / 64, T_TOK / 128, E_NUM), 256>>>(w2);
    combine_kernel<<<T_TOK, 256>>>(out);
}

// round 3
// speedup vs baseline: 3.6172x; 3.6172x over previous
#include <cuda_runtime.h>
#include <cuda_fp16.h>
#include <cuda_bf16.h>
#include <mma.h>
#include <cstdint>
#include <cstddef>

using namespace nvcuda;

#define T_TOK 2048
#define H_DIM 2048
#define I_DIM 1024
#define E_NUM 16
#define K_TOP 4
#define NPAIR (T_TOK * K_TOP)
#define WELEM (E_NUM * H_DIM * I_DIM)   // 33,554,432 per weight tensor

// ---------------- static device scratch ----------------
__device__ int    g_topk_idx[T_TOK * K_TOP];
__device__ float  g_topk_w[T_TOK * K_TOP];
__device__ int    g_counts[E_NUM];
__device__ int    g_off[E_NUM];
__device__ int    g_srcTok[NPAIR];
__device__ int    g_rowOf[T_TOK * K_TOP];
__device__ __half g_hh[(size_t)T_TOK * H_DIM];       // fp16 hidden
__device__ __half g_w1h[(size_t)WELEM];              // fp16 weights
__device__ __half g_w3h[(size_t)WELEM];
__device__ __half g_w2h[(size_t)WELEM];
__device__ __half g_act[(size_t)NPAIR * I_DIM];      // SwiGLU activations
__device__ float  g_dout[(size_t)NPAIR * H_DIM];     // per-pair down proj (unscaled)

// ---------------- cp.async helpers ----------------
__device__ __forceinline__ void cp_async16(void* smem, const void* g, bool pred) {
    unsigned s = (unsigned)__cvta_generic_to_shared(smem);
    int sz = pred ? 16 : 0;
    asm volatile("cp.async.cg.shared.global [%0], [%1], 16, %2;\n" :: "r"(s), "l"(g), "r"(sz));
}
__device__ __forceinline__ void cp_async8(void* smem, const void* g, bool pred) {
    unsigned s = (unsigned)__cvta_generic_to_shared(smem);
    int sz = pred ? 8 : 0;
    asm volatile("cp.async.ca.shared.global [%0], [%1], 8, %2;\n" :: "r"(s), "l"(g), "r"(sz));
}
__device__ __forceinline__ void cp_commit() { asm volatile("cp.async.commit_group;\n"); }
__device__ __forceinline__ void cp_wait1()  { asm volatile("cp.async.wait_group 1;\n"); }
__device__ __forceinline__ void cp_wait0()  { asm volatile("cp.async.wait_group 0;\n"); }

// ---------------- init ----------------
__global__ void init_kernel() {
    if (threadIdx.x < E_NUM) g_counts[threadIdx.x] = 0;
}

// ---------------- weight fp32 -> fp16 convert ----------------
__global__ void convert_kernel(const float* __restrict__ src, __half* __restrict__ dst, int n4) {
    const float4* s4 = (const float4*)src;
    __half2* d2 = (__half2*)dst;
    for (int i = blockIdx.x * blockDim.x + threadIdx.x; i < n4; i += gridDim.x * blockDim.x) {
        float4 v = s4[i];
        d2[i * 2]     = __floats2half2_rn(v.x, v.y);
        d2[i * 2 + 1] = __floats2half2_rn(v.z, v.w);
    }
}

// ---------------- router (fp32) + hidden fp16 conversion ----------------
__global__ void router_kernel(const float* __restrict__ hidden,
                              const float* __restrict__ gate_w) {
    int t = blockIdx.x;
    __shared__ float sh[H_DIM];
    __shared__ float slog[E_NUM];
    int tid = threadIdx.x;                 // 128
    for (int i = tid; i < H_DIM; i += 128) {
        float v = hidden[(size_t)t * H_DIM + i];
        sh[i] = v;
        g_hh[(size_t)t * H_DIM + i] = __float2half(v);
    }
    __syncthreads();
    int wid = tid >> 5, lane = tid & 31;
    for (int q = 0; q < 4; q++) {
        int e = wid * 4 + q;
        const float* g = gate_w + (size_t)e * H_DIM;
        float p = 0.f;
        for (int i = lane; i < H_DIM; i += 32) p += sh[i] * g[i];
        #pragma unroll
        for (int o = 16; o > 0; o >>= 1) p += __shfl_down_sync(0xffffffffu, p, o);
        if (lane == 0) slog[e] = p;
    }
    __syncthreads();
    if (tid == 0) {
        float mx = -1e30f;
        for (int e = 0; e < E_NUM; e++) mx = fmaxf(mx, slog[e]);
        float pr[E_NUM];
        for (int e = 0; e < E_NUM; e++) pr[e] = __expf(slog[e] - mx);
        int idx[K_TOP]; float w[K_TOP];
        for (int k = 0; k < K_TOP; k++) {
            float bv = -1.f; int bi = 0;
            for (int e = 0; e < E_NUM; e++) {
                bool used = false;
                for (int kk = 0; kk < k; kk++) if (idx[kk] == e) used = true;
                if (!used && pr[e] > bv) { bv = pr[e]; bi = e; }
            }
            idx[k] = bi; w[k] = bv;
        }
        float inv = 1.f / (w[0] + w[1] + w[2] + w[3]);
        for (int k = 0; k < K_TOP; k++) {
            g_topk_idx[t * K_TOP + k] = idx[k];
            g_topk_w[t * K_TOP + k]   = w[k] * inv;
            atomicAdd(&g_counts[idx[k]], 1);
        }
    }
}

__global__ void prefix_kernel() {
    if (threadIdx.x == 0) {
        int acc = 0;
        for (int e = 0; e < E_NUM; e++) { g_off[e] = acc; acc += g_counts[e]; }
    }
}

__global__ void fill_kernel() {
    int e = blockIdx.x;
    int start = g_off[e];
    __shared__ int s_counter, s_prefix[8], s_wsum[8];
    int tid = threadIdx.x, lane = tid & 31, wid = tid >> 5;
    if (tid == 0) s_counter = 0;
    __syncthreads();
    for (int base = 0; base < T_TOK; base += 256) {
        int t = base + tid;
        int myk = -1;
        #pragma unroll
        for (int k = 0; k < K_TOP; k++) if (g_topk_idx[t * K_TOP + k] == e) myk = k;
        unsigned bal = __ballot_sync(0xffffffffu, myk >= 0);
        if (lane == 0) s_wsum[wid] = __popc(bal);
        __syncthreads();
        if (tid == 0) {
            int acc = s_counter;
            for (int w = 0; w < 8; w++) { s_prefix[w] = acc; acc += s_wsum[w]; }
            s_counter = acc;
        }
        __syncthreads();
        if (myk >= 0) {
            int j = s_prefix[wid] + __popc(bal & ((1u << lane) - 1));
            int r = start + j;
            g_srcTok[r] = t;
            g_rowOf[t * K_TOP + myk] = r;
        }
        __syncthreads();
    }
}

// ---------------- GEMM1: act = silu(X@W1)*(X@W3). BM=128 BN=64 BK=32, cp.async x2 buffer ----------------
__global__ __launch_bounds__(256) void gemm1_kernel() {
    int e = blockIdx.z;
    int M_e = g_counts[e];
    int mbase = blockIdx.y * 128;
    if (mbase >= M_e) return;
    int n0 = blockIdx.x * 64;
    int rstart = g_off[e] + mbase;
    int mrem = M_e - mbase; if (mrem > 128) mrem = 128;

    __shared__ __align__(16) __half Ah[2][128][40];
    __shared__ __align__(16) __half B1h[2][32][72];
    __shared__ __align__(16) __half B3h[2][32][72];
    __shared__ int rows[128];
    float (*stage)[16][20] = (float(*)[16][20])(&Ah[0][0][0]);  // aliases Ah (epilogue only)

    int tid = threadIdx.x;
    if (tid < 128) rows[tid] = (tid < mrem) ? g_srcTok[rstart + tid] : 0;
    __syncthreads();

    const __half* w1b = g_w1h + (size_t)e * H_DIM * I_DIM + n0;
    const __half* w3b = g_w3h + (size_t)e * H_DIM * I_DIM + n0;

    auto load_stage = [&](int buf, int k0) {
        // A: 128 rows x 32 halves, 8B chunks -> 4 per thread
        #pragma unroll
        for (int p = 0; p < 4; p++) {
            int idx = tid + p * 256;
            int m = idx >> 3, seg = idx & 7;
            cp_async8(&Ah[buf][m][seg * 4],
                      g_hh + (size_t)rows[m] * H_DIM + k0 + seg * 4, m < mrem);
        }
        // B1/B3: 32 rows x 64 halves, 16B chunks -> 1 each per thread
        {
            int kb = tid >> 3, seg = tid & 7;
            const __half* s1 = w1b + (size_t)(k0 + kb) * I_DIM + seg * 8;
            const __half* s3 = w3b + (size_t)(k0 + kb) * I_DIM + seg * 8;
            cp_async16(&B1h[buf][kb][seg * 8], s1, true);
            cp_async16(&B3h[buf][kb][seg * 8], s3, true);
        }
    };

    wmma::fragment<wmma::accumulator, 16, 16, 16, float> acc1[2][2], acc3[2][2];
    #pragma unroll
    for (int i = 0; i < 2; i++)
        #pragma unroll
        for (int j = 0; j < 2; j++) {
            wmma::fill_fragment(acc1[i][j], 0.f);
            wmma::fill_fragment(acc3[i][j], 0.f);
        }

    int wid = tid >> 5, lane = tid & 31;
    int wm = wid & 3, wn = wid >> 2;       // 4 x 2 warps, warp tile 32x32 (x2 outputs)

    load_stage(0, 0);
    cp_commit();

    const int KT = H_DIM / 32;   // 64
    for (int kt = 0; kt < KT; kt++) {
        int buf = kt & 1;
        if (kt + 1 < KT) { load_stage(buf ^ 1, (kt + 1) * 32); cp_commit(); cp_wait1(); }
        else             { cp_wait0(); }
        __syncthreads();
        #pragma unroll
        for (int kk = 0; kk < 32; kk += 16) {
            wmma::fragment<wmma::matrix_a, 16, 16, 16, __half, wmma::row_major> af[2];
            wmma::load_matrix_sync(af[0], &Ah[buf][wm * 32][kk], 40);
            wmma::load_matrix_sync(af[1], &Ah[buf][wm * 32 + 16][kk], 40);
            wmma::fragment<wmma::matrix_b, 16, 16, 16, __half, wmma::row_major> bf1[2], bf3[2];
            #pragma unroll
            for (int j = 0; j < 2; j++) {
                wmma::load_matrix_sync(bf1[j], &B1h[buf][kk][wn * 32 + j * 16], 72);
                wmma::load_matrix_sync(bf3[j], &B3h[buf][kk][wn * 32 + j * 16], 72);
            }
            #pragma unroll
            for (int i = 0; i < 2; i++)
                #pragma unroll
                for (int j = 0; j < 2; j++) {
                    wmma::mma_sync(acc1[i][j], af[i], bf1[j], acc1[i][j]);
                    wmma::mma_sync(acc3[i][j], af[i], bf3[j], acc3[i][j]);
                }
        }
        __syncthreads();
    }

    // Epilogue: silu(h1)*h3 -> fp16
    #pragma unroll
    for (int i = 0; i < 2; i++)
        #pragma unroll
        for (int j = 0; j < 2; j++) {
            #pragma unroll
            for (int x = 0; x < acc1[i][j].num_elements; x++) {
                float a = acc1[i][j].x[x];
                float sig = 1.0f / (1.0f + __expf(-a));
                acc1[i][j].x[x] = a * sig * acc3[i][j].x[x];
            }
            wmma::store_matrix_sync(&stage[wid][0][0], acc1[i][j], 20, wmma::mem_row_major);
            __syncwarp();
            for (int s2 = lane; s2 < 256; s2 += 32) {
                int rr = s2 >> 4, cc = s2 & 15;
                int m = wm * 32 + i * 16 + rr;
                if (m < mrem)
                    g_act[(size_t)(rstart + m) * I_DIM + n0 + wn * 32 + j * 16 + cc] =
                        __float2half(stage[wid][rr][cc]);
            }
            __syncwarp();
        }
}

// ---------------- GEMM2: dout = act @ W2 (scale deferred to combine). BM=128 BN=128 BK=32 ----------------
__global__ __launch_bounds__(256) void gemm2_kernel() {
    int e = blockIdx.z;
    int M_e = g_counts[e];
    int mbase = blockIdx.y * 128;
    if (mbase >= M_e) return;
    int n0 = blockIdx.x * 128;
    int rstart = g_off[e] + mbase;
    int mrem = M_e - mbase; if (mrem > 128) mrem = 128;

    __shared__ __align__(16) __half Ah[2][128][40];
    __shared__ __align__(16) __half Bh[2][32][136];
    float (*stage)[16][20] = (float(*)[16][20])(&Ah[0][0][0]);

    int tid = threadIdx.x;
    const __half* w2b = g_w2h + (size_t)e * I_DIM * H_DIM + n0;

    auto load_stage = [&](int buf, int k0) {
        #pragma unroll
        for (int p = 0; p < 4; p++) {
            int idx = tid + p * 256;
            int m = idx >> 3, seg = idx & 7;
            cp_async8(&Ah[buf][m][seg * 4],
                      g_act + (size_t)(rstart + m) * I_DIM + k0 + seg * 4, m < mrem);
        }
        #pragma unroll
        for (int p = 0; p < 2; p++) {
            int idx = tid + p * 256;
            int kb = idx >> 4, seg = idx & 15;
            cp_async16(&Bh[buf][kb][seg * 8],
                       w2b + (size_t)(k0 + kb) * H_DIM + seg * 8, true);
        }
    };

    wmma::fragment<wmma::accumulator, 16, 16, 16, float> acc[2][4];
    #pragma unroll
    for (int i = 0; i < 2; i++)
        #pragma unroll
        for (int j = 0; j < 4; j++) wmma::fill_fragment(acc[i][j], 0.f);

    int wid = tid >> 5, lane = tid & 31;
    int wm = wid & 3, wn = wid >> 2;       // 4 x 2 warps, warp tile 32 x 64

    load_stage(0, 0);
    cp_commit();

    const int KT = I_DIM / 32;   // 32
    for (int kt = 0; kt < KT; kt++) {
        int buf = kt & 1;
        if (kt + 1 < KT) { load_stage(buf ^ 1, (kt + 1) * 32); cp_commit(); cp_wait1(); }
        else             { cp_wait0(); }
        __syncthreads();
        #pragma unroll
        for (int kk = 0; kk < 32; kk += 16) {
            wmma::fragment<wmma::matrix_a, 16, 16, 16, __half, wmma::row_major> af[2];
            wmma::load_matrix_sync(af[0], &Ah[buf][wm * 32][kk], 40);
            wmma::load_matrix_sync(af[1], &Ah[buf][wm * 32 + 16][kk], 40);
            wmma::fragment<wmma::matrix_b, 16, 16, 16, __half, wmma::row_major> bf[4];
            #pragma unroll
            for (int j = 0; j < 4; j++)
                wmma::load_matrix_sync(bf[j], &Bh[buf][kk][wn * 64 + j * 16], 136);
            #pragma unroll
            for (int i = 0; i < 2; i++)
                #pragma unroll
                for (int j = 0; j < 4; j++)
                    wmma::mma_sync(acc[i][j], af[i], bf[j], acc[i][j]);
        }
        __syncthreads();
    }

    if (mrem == 128) {
        // full tile: store fp32 accumulators straight to global
        #pragma unroll
        for (int i = 0; i < 2; i++)
            #pragma unroll
            for (int j = 0; j < 4; j++) {
                float* dst = g_dout + (size_t)(rstart + wm * 32 + i * 16) * H_DIM
                                    + n0 + wn * 64 + j * 16;
                wmma::store_matrix_sync(dst, acc[i][j], H_DIM, wmma::mem_row_major);
            }
    } else {
        #pragma unroll
        for (int i = 0; i < 2; i++)
            #pragma unroll
            for (int j = 0; j < 4; j++) {
                wmma::store_matrix_sync(&stage[wid][0][0], acc[i][j], 20, wmma::mem_row_major);
                __syncwarp();
                for (int s2 = lane; s2 < 256; s2 += 32) {
                    int rr = s2 >> 4, cc = s2 & 15;
                    int m = wm * 32 + i * 16 + rr;
                    if (m < mrem)
                        g_dout[(size_t)(rstart + m) * H_DIM + n0 + wn * 64 + j * 16 + cc] =
                            stage[wid][rr][cc];
                }
                __syncwarp();
            }
    }
}

// ---------------- combine: out[t] = sum_k w_k * dout[rowOf[t][k]] ----------------
__global__ void combine_kernel(float* __restrict__ out) {
    int t = blockIdx.x;
    int r0 = g_rowOf[t * K_TOP + 0], r1 = g_rowOf[t * K_TOP + 1];
    int r2 = g_rowOf[t * K_TOP + 2], r3 = g_rowOf[t * K_TOP + 3];
    float w0 = g_topk_w[t * K_TOP + 0], w1 = g_topk_w[t * K_TOP + 1];
    float w2 = g_topk_w[t * K_TOP + 2], w3 = g_topk_w[t * K_TOP + 3];
    const float4* d0 = (const float4*)(g_dout + (size_t)r0 * H_DIM);
    const float4* d1 = (const float4*)(g_dout + (size_t)r1 * H_DIM);
    const float4* d2 = (const float4*)(g_dout + (size_t)r2 * H_DIM);
    const float4* d3 = (const float4*)(g_dout + (size_t)r3 * H_DIM);
    float4* o = (float4*)(out + (size_t)t * H_DIM);
    for (int i = threadIdx.x; i < H_DIM / 4; i += 256) {
        float4 a = d0[i], b = d1[i], c = d2[i], d = d3[i];
        float4 r;
        r.x = w0 * a.x + w1 * b.x + w2 * c.x + w3 * d.x;
        r.y = w0 * a.y + w1 * b.y + w2 * c.y + w3 * d.y;
        r.z = w0 * a.z + w1 * b.z + w2 * c.z + w3 * d.z;
        r.w = w0 * a.w + w1 * b.w + w2 * c.w + w3 * d.w;
        o[i] = r;
    }
}

// ---------------- launch ----------------
extern "C" void kernel_launch(void* const* d_in, const int* in_sizes, int n_in,
                              void* d_out, int out_size) {
    const float* hidden = (const float*)d_in[0];
    const float* gate_w = (const float*)d_in[1];
    const float* w1     = (const float*)d_in[2];
    const float* w3     = (const float*)d_in[3];
    const float* w2     = (const float*)d_in[4];
    float* out = (float*)d_out;

    __half *w1h, *w3h, *w2h;
    cudaGetSymbolAddress((void**)&w1h, g_w1h);
    cudaGetSymbolAddress((void**)&w3h, g_w3h);
    cudaGetSymbolAddress((void**)&w2h, g_w2h);

    init_kernel<<<1, 32>>>();
    convert_kernel<<<2048, 256>>>(w1, w1h, WELEM / 4);
    convert_kernel<<<2048, 256>>>(w3, w3h, WELEM / 4);
    convert_kernel<<<2048, 256>>>(w2, w2h, WELEM / 4);
    router_kernel<<<T_TOK, 128>>>(hidden, gate_w);
    prefix_kernel<<<1, 32>>>();
    fill_kernel<<<E_NUM, 256>>>();
    gemm1_kernel<<<dim3(I_DIM / 64, 16, E_NUM), 256>>>();
    gemm2_kernel<<<dim3(H_DIM / 128, 16, E_NUM), 256>>>();
    combine_kernel<<<T_TOK, 256>>>(out);
}

// round 5
// speedup vs baseline: 4.0583x; 1.1219x over previous
#include <cuda_runtime.h>
#include <cuda_fp16.h>
#include <cstdint>
#include <cstddef>

#define T_TOK 2048
#define H_DIM 2048
#define I_DIM 1024
#define E_NUM 16
#define K_TOP 4
#define NPAIR (T_TOK * K_TOP)
#define WELEM (E_NUM * H_DIM * I_DIM)

// ---------------- static device scratch ----------------
__device__ int    g_topk_idx[T_TOK * K_TOP];
__device__ float  g_topk_w[T_TOK * K_TOP];
__device__ int    g_counts[E_NUM];
__device__ int    g_off[E_NUM];
__device__ int    g_srcTok[NPAIR];
__device__ int    g_rowOf[T_TOK * K_TOP];
__device__ __half g_hh[(size_t)T_TOK * H_DIM];       // fp16 hidden [T, H]
__device__ __half g_w13[(size_t)2 * WELEM];          // fp16 interleaved (w1,w3) [E][H][2I]
__device__ __half g_w2h[(size_t)WELEM];              // fp16 w2 [E][I][H]
__device__ __half g_act[(size_t)NPAIR * I_DIM];      // SwiGLU activations
__device__ float  g_dout[(size_t)NPAIR * H_DIM];     // per-pair down proj (unscaled)

// ---------------- helpers ----------------
__device__ __forceinline__ uint32_t smem_u32(const void* p) {
    return (uint32_t)__cvta_generic_to_shared(p);
}
__device__ __forceinline__ void cpa16(uint32_t s, const void* g) {
    asm volatile("cp.async.cg.shared.global [%0], [%1], 16;\n" :: "r"(s), "l"(g));
}
__device__ __forceinline__ void cp_commit() { asm volatile("cp.async.commit_group;\n"); }
__device__ __forceinline__ void cp_wait2()  { asm volatile("cp.async.wait_group 2;\n"); }
__device__ __forceinline__ void cp_wait1()  { asm volatile("cp.async.wait_group 1;\n"); }
__device__ __forceinline__ void cp_wait0()  { asm volatile("cp.async.wait_group 0;\n"); }

__device__ __forceinline__ void ldsm_x4(uint32_t& r0, uint32_t& r1, uint32_t& r2, uint32_t& r3,
                                        uint32_t addr) {
    asm volatile("ldmatrix.sync.aligned.m8n8.x4.shared.b16 {%0,%1,%2,%3}, [%4];"
                 : "=r"(r0), "=r"(r1), "=r"(r2), "=r"(r3) : "r"(addr));
}
__device__ __forceinline__ void ldsm_x4t(uint32_t& r0, uint32_t& r1, uint32_t& r2, uint32_t& r3,
                                         uint32_t addr) {
    asm volatile("ldmatrix.sync.aligned.m8n8.x4.trans.shared.b16 {%0,%1,%2,%3}, [%4];"
                 : "=r"(r0), "=r"(r1), "=r"(r2), "=r"(r3) : "r"(addr));
}
__device__ __forceinline__ void mma16816(float* d, uint32_t a0, uint32_t a1, uint32_t a2,
                                         uint32_t a3, uint32_t b0, uint32_t b1) {
    asm volatile(
        "mma.sync.aligned.m16n8k16.row.col.f32.f16.f16.f32 "
        "{%0,%1,%2,%3}, {%4,%5,%6,%7}, {%8,%9}, {%0,%1,%2,%3};"
        : "+f"(d[0]), "+f"(d[1]), "+f"(d[2]), "+f"(d[3])
        : "r"(a0), "r"(a1), "r"(a2), "r"(a3), "r"(b0), "r"(b1));
}

// ---------------- init ----------------
__global__ void init_kernel() {
    if (threadIdx.x < E_NUM) g_counts[threadIdx.x] = 0;
}

// ---------------- converts ----------------
// w1,w3 [E][H][I] fp32 -> interleaved fp16 [E][H][2I]: out[2i]=w1[i], out[2i+1]=w3[i]
__global__ void interleave_convert(const float* __restrict__ w1, const float* __restrict__ w3,
                                   __half* __restrict__ dst, int n4) {
    const float4* a4 = (const float4*)w1;
    const float4* b4 = (const float4*)w3;
    uint4* d4 = (uint4*)dst;   // 8 halfs
    for (int i = blockIdx.x * blockDim.x + threadIdx.x; i < n4; i += gridDim.x * blockDim.x) {
        float4 a = a4[i], b = b4[i];
        __half2 h0 = __floats2half2_rn(a.x, b.x);
        __half2 h1 = __floats2half2_rn(a.y, b.y);
        __half2 h2 = __floats2half2_rn(a.z, b.z);
        __half2 h3 = __floats2half2_rn(a.w, b.w);
        uint4 o;
        o.x = *(uint32_t*)&h0; o.y = *(uint32_t*)&h1;
        o.z = *(uint32_t*)&h2; o.w = *(uint32_t*)&h3;
        d4[i] = o;
    }
}
__global__ void convert_kernel(const float* __restrict__ src, __half* __restrict__ dst, int n4) {
    const float4* s4 = (const float4*)src;
    __half2* d2 = (__half2*)dst;
    for (int i = blockIdx.x * blockDim.x + threadIdx.x; i < n4; i += gridDim.x * blockDim.x) {
        float4 v = s4[i];
        d2[i * 2]     = __floats2half2_rn(v.x, v.y);
        d2[i * 2 + 1] = __floats2half2_rn(v.z, v.w);
    }
}

// ---------------- router (fp32) + hidden fp16 conversion ----------------
__global__ void router_kernel(const float* __restrict__ hidden,
                              const float* __restrict__ gate_w) {
    int t = blockIdx.x;
    __shared__ float sh[H_DIM];
    __shared__ float slog[E_NUM];
    int tid = threadIdx.x;                 // 128
    for (int i = tid; i < H_DIM; i += 128) {
        float v = hidden[(size_t)t * H_DIM + i];
        sh[i] = v;
        g_hh[(size_t)t * H_DIM + i] = __float2half(v);
    }
    __syncthreads();
    int wid = tid >> 5, lane = tid & 31;
    for (int q = 0; q < 4; q++) {
        int e = wid * 4 + q;
        const float* g = gate_w + (size_t)e * H_DIM;
        float p = 0.f;
        for (int i = lane; i < H_DIM; i += 32) p += sh[i] * g[i];
        #pragma unroll
        for (int o = 16; o > 0; o >>= 1) p += __shfl_down_sync(0xffffffffu, p, o);
        if (lane == 0) slog[e] = p;
    }
    __syncthreads();
    if (tid == 0) {
        float mx = -1e30f;
        for (int e = 0; e < E_NUM; e++) mx = fmaxf(mx, slog[e]);
        float pr[E_NUM];
        for (int e = 0; e < E_NUM; e++) pr[e] = __expf(slog[e] - mx);
        int idx[K_TOP]; float w[K_TOP];
        for (int k = 0; k < K_TOP; k++) {
            float bv = -1.f; int bi = 0;
            for (int e = 0; e < E_NUM; e++) {
                bool used = false;
                for (int kk = 0; kk < k; kk++) if (idx[kk] == e) used = true;
                if (!used && pr[e] > bv) { bv = pr[e]; bi = e; }
            }
            idx[k] = bi; w[k] = bv;
        }
        float inv = 1.f / (w[0] + w[1] + w[2] + w[3]);
        for (int k = 0; k < K_TOP; k++) {
            g_topk_idx[t * K_TOP + k] = idx[k];
            g_topk_w[t * K_TOP + k]   = w[k] * inv;
            atomicAdd(&g_counts[idx[k]], 1);
        }
    }
}

__global__ void prefix_kernel() {
    if (threadIdx.x == 0) {
        int acc = 0;
        for (int e = 0; e < E_NUM; e++) { g_off[e] = acc; acc += g_counts[e]; }
    }
}

__global__ void fill_kernel() {
    int e = blockIdx.x;
    int start = g_off[e];
    __shared__ int s_counter, s_prefix[8], s_wsum[8];
    int tid = threadIdx.x, lane = tid & 31, wid = tid >> 5;
    if (tid == 0) s_counter = 0;
    __syncthreads();
    for (int base = 0; base < T_TOK; base += 256) {
        int t = base + tid;
        int myk = -1;
        #pragma unroll
        for (int k = 0; k < K_TOP; k++) if (g_topk_idx[t * K_TOP + k] == e) myk = k;
        unsigned bal = __ballot_sync(0xffffffffu, myk >= 0);
        if (lane == 0) s_wsum[wid] = __popc(bal);
        __syncthreads();
        if (tid == 0) {
            int acc = s_counter;
            for (int w = 0; w < 8; w++) { s_prefix[w] = acc; acc += s_wsum[w]; }
            s_counter = acc;
        }
        __syncthreads();
        if (myk >= 0) {
            int j = s_prefix[wid] + __popc(bal & ((1u << lane) - 1));
            int r = start + j;
            g_srcTok[r] = t;
            g_rowOf[t * K_TOP + myk] = r;
        }
        __syncthreads();
    }
}

// ---------------- GEMM smem layout (dynamic) ----------------
// rows[128] at 0, 3 stages at 1024: A [128][40] halfs (10240B), B [32][136] halfs (8704B)
#define A_PITCH 40
#define B_PITCH 136
#define A_BYTES (128 * A_PITCH * 2)
#define STAGE_BYTES (A_BYTES + 32 * B_PITCH * 2)
#define SM_STAGE0 1024
#define SM_BYTES (SM_STAGE0 + 3 * STAGE_BYTES)

// Shared mainloop macro body implemented as a template over epilogue via two kernels.

// ---------------- GEMM1: [128 rows] x K=2048 -> 64 I-cols (interleaved pairs) ----------------
__global__ __launch_bounds__(256, 2) void gemm1_kernel() {
    int e = blockIdx.z;
    int M_e = g_counts[e];
    int mbase = blockIdx.y * 128;
    if (mbase >= M_e) return;
    int n0o = blockIdx.x * 64;                 // output cols over I
    int rstart = g_off[e] + mbase;
    int mrem = M_e - mbase; if (mrem > 128) mrem = 128;

    extern __shared__ __align__(16) char smem[];
    int* rows_s = (int*)smem;
    uint32_t sb = smem_u32(smem);
    int tid = threadIdx.x, lane = tid & 31;
    int warp = tid >> 5, wm = warp >> 2, wn = warp & 3;

    if (tid < 128) rows_s[tid] = (tid < mrem) ? g_srcTok[rstart + tid] : 0;
    __syncthreads();

    const __half* wb = g_w13 + (size_t)e * H_DIM * (2 * I_DIM) + 2 * n0o;

    // per-thread cp.async source setup
    int am = tid >> 2, aseg = tid & 3;             // A: 2 chunks (m, m+64)
    const __half* asrc0 = g_hh + (size_t)rows_s[am] * H_DIM + aseg * 8;
    const __half* asrc1 = g_hh + (size_t)rows_s[am + 64] * H_DIM + aseg * 8;
    uint32_t adst0 = sb + SM_STAGE0 + am * (A_PITCH * 2) + aseg * 16;
    uint32_t adst1 = sb + SM_STAGE0 + (am + 64) * (A_PITCH * 2) + aseg * 16;
    int bk = tid >> 4, bseg = tid & 15;            // B: 2 chunks (k, k+16)
    const __half* bsrc0 = wb + (size_t)bk * (2 * I_DIM) + bseg * 8;
    const __half* bsrc1 = wb + (size_t)(bk + 16) * (2 * I_DIM) + bseg * 8;
    uint32_t bdst0 = sb + SM_STAGE0 + A_BYTES + bk * (B_PITCH * 2) + bseg * 16;
    uint32_t bdst1 = sb + SM_STAGE0 + A_BYTES + (bk + 16) * (B_PITCH * 2) + bseg * 16;

    // ldmatrix base offsets (relative to stage base)
    uint32_t aoff[4], boff[2];
    #pragma unroll
    for (int mf = 0; mf < 4; mf++)
        aoff[mf] = (wm * 64 + mf * 16 + (lane & 15)) * (A_PITCH * 2) + (lane >> 4) * 16;
    #pragma unroll
    for (int p = 0; p < 2; p++)
        boff[p] = A_BYTES + ((lane & 7) + 8 * ((lane >> 3) & 1)) * (B_PITCH * 2)
                + (wn * 32 + p * 16 + 8 * (lane >> 4)) * 2;

    float acc[4][4][4];
    #pragma unroll
    for (int i = 0; i < 4; i++)
        #pragma unroll
        for (int j = 0; j < 4; j++)
            #pragma unroll
            for (int r = 0; r < 4; r++) acc[i][j][r] = 0.f;

    auto issue = [&](int s) {
        uint32_t so = (uint32_t)((s % 3) * STAGE_BYTES);
        size_t ko = (size_t)s * 32;
        cpa16(adst0 + so, asrc0 + ko);
        cpa16(adst1 + so, asrc1 + ko);
        cpa16(bdst0 + so, bsrc0 + ko * (2 * I_DIM) / 32 * 32);  // dummy-free below
        cpa16(bdst1 + so, bsrc1 + ko * 0 + (size_t)s * 32 * (2 * I_DIM));
        cp_commit();
    };
    // note: B advances along H (rows) by s*32 rows
    // rewrite issue without the confusing arithmetic:
    auto issue2 = [&](int s) {
        uint32_t so = (uint32_t)((s % 3) * STAGE_BYTES);
        size_t ka = (size_t)s * 32;                       // A col offset (halfs)
        size_t kb = (size_t)s * 32 * (2 * I_DIM);         // B row offset (halfs)
        cpa16(adst0 + so, asrc0 + ka);
        cpa16(adst1 + so, asrc1 + ka);
        cpa16(bdst0 + so, bsrc0 + kb);
        cpa16(bdst1 + so, bsrc1 + kb);
        cp_commit();
    };
    (void)issue;

    const int NS = H_DIM / 32;   // 64
    issue2(0); issue2(1); issue2(2);
    for (int s = 0; s < NS; s++) {
        int w = NS - 1 - s;
        if (w >= 2) cp_wait2(); else if (w == 1) cp_wait1(); else cp_wait0();
        __syncthreads();
        uint32_t sbase = sb + SM_STAGE0 + (uint32_t)((s % 3) * STAGE_BYTES);
        #pragma unroll
        for (int kk = 0; kk < 2; kk++) {
            uint32_t a[4][4], b[2][4];
            #pragma unroll
            for (int mf = 0; mf < 4; mf++)
                ldsm_x4(a[mf][0], a[mf][1], a[mf][2], a[mf][3],
                        sbase + aoff[mf] + kk * 32);                    // +16 halfs
            #pragma unroll
            for (int p = 0; p < 2; p++)
                ldsm_x4t(b[p][0], b[p][1], b[p][2], b[p][3],
                         sbase + boff[p] + kk * 16 * (B_PITCH * 2));    // +16 k-rows
            #pragma unroll
            for (int mf = 0; mf < 4; mf++) {
                #pragma unroll
                for (int p = 0; p < 2; p++) {
                    mma16816(acc[mf][p * 2],     a[mf][0], a[mf][1], a[mf][2], a[mf][3],
                             b[p][0], b[p][1]);
                    mma16816(acc[mf][p * 2 + 1], a[mf][0], a[mf][1], a[mf][2], a[mf][3],
                             b[p][2], b[p][3]);
                }
            }
        }
        __syncthreads();
        if (s + 3 < NS) issue2(s + 3);
    }

    // epilogue: interleaved pairs (c0=w1, c1=w3) -> silu(c0)*c1, fp16 store
    #pragma unroll
    for (int mf = 0; mf < 4; mf++) {
        int r0 = wm * 64 + mf * 16 + (lane >> 2);
        #pragma unroll
        for (int nf = 0; nf < 4; nf++) {
            int col = n0o + wn * 16 + nf * 4 + (lane & 3);
            float x0 = acc[mf][nf][0], y0 = acc[mf][nf][1];
            float x1 = acc[mf][nf][2], y1 = acc[mf][nf][3];
            float v0 = x0 / (1.0f + __expf(-x0)) * y0;
            float v1 = x1 / (1.0f + __expf(-x1)) * y1;
            if (r0 < mrem)     g_act[(size_t)(rstart + r0) * I_DIM + col]     = __float2half(v0);
            if (r0 + 8 < mrem) g_act[(size_t)(rstart + r0 + 8) * I_DIM + col] = __float2half(v1);
        }
    }
}

// ---------------- GEMM2: dout[128, 128H] = act[128, I] x w2h ----------------
__global__ __launch_bounds__(256, 2) void gemm2_kernel() {
    int e = blockIdx.z;
    int M_e = g_counts[e];
    int mbase = blockIdx.y * 128;
    if (mbase >= M_e) return;
    int n0 = blockIdx.x * 128;                // over H
    int rstart = g_off[e] + mbase;
    int mrem = M_e - mbase; if (mrem > 128) mrem = 128;

    extern __shared__ __align__(16) char smem[];
    uint32_t sb = smem_u32(smem);
    int tid = threadIdx.x, lane = tid & 31;
    int warp = tid >> 5, wm = warp >> 2, wn = warp & 3;

    const __half* wb = g_w2h + (size_t)e * I_DIM * H_DIM + n0;

    int am = tid >> 2, aseg = tid & 3;
    int ar0 = rstart + am;      if (ar0 >= NPAIR) ar0 = NPAIR - 1;
    int ar1 = rstart + am + 64; if (ar1 >= NPAIR) ar1 = NPAIR - 1;
    const __half* asrc0 = g_act + (size_t)ar0 * I_DIM + aseg * 8;
    const __half* asrc1 = g_act + (size_t)ar1 * I_DIM + aseg * 8;
    uint32_t adst0 = sb + SM_STAGE0 + am * (A_PITCH * 2) + aseg * 16;
    uint32_t adst1 = sb + SM_STAGE0 + (am + 64) * (A_PITCH * 2) + aseg * 16;
    int bk = tid >> 4, bseg = tid & 15;
    const __half* bsrc0 = wb + (size_t)bk * H_DIM + bseg * 8;
    const __half* bsrc1 = wb + (size_t)(bk + 16) * H_DIM + bseg * 8;
    uint32_t bdst0 = sb + SM_STAGE0 + A_BYTES + bk * (B_PITCH * 2) + bseg * 16;
    uint32_t bdst1 = sb + SM_STAGE0 + A_BYTES + (bk + 16) * (B_PITCH * 2) + bseg * 16;

    uint32_t aoff[4], boff[2];
    #pragma unroll
    for (int mf = 0; mf < 4; mf++)
        aoff[mf] = (wm * 64 + mf * 16 + (lane & 15)) * (A_PITCH * 2) + (lane >> 4) * 16;
    #pragma unroll
    for (int p = 0; p < 2; p++)
        boff[p] = A_BYTES + ((lane & 7) + 8 * ((lane >> 3) & 1)) * (B_PITCH * 2)
                + (wn * 32 + p * 16 + 8 * (lane >> 4)) * 2;

    float acc[4][4][4];
    #pragma unroll
    for (int i = 0; i < 4; i++)
        #pragma unroll
        for (int j = 0; j < 4; j++)
            #pragma unroll
            for (int r = 0; r < 4; r++) acc[i][j][r] = 0.f;

    auto issue = [&](int s) {
        uint32_t so = (uint32_t)((s % 3) * STAGE_BYTES);
        size_t ka = (size_t)s * 32;               // A col offset
        size_t kb = (size_t)s * 32 * H_DIM;       // B row offset
        cpa16(adst0 + so, asrc0 + ka);
        cpa16(adst1 + so, asrc1 + ka);
        cpa16(bdst0 + so, bsrc0 + kb);
        cpa16(bdst1 + so, bsrc1 + kb);
        cp_commit();
    };

    const int NS = I_DIM / 32;   // 32
    issue(0); issue(1); issue(2);
    for (int s = 0; s < NS; s++) {
        int w = NS - 1 - s;
        if (w >= 2) cp_wait2(); else if (w == 1) cp_wait1(); else cp_wait0();
        __syncthreads();
        uint32_t sbase = sb + SM_STAGE0 + (uint32_t)((s % 3) * STAGE_BYTES);
        #pragma unroll
        for (int kk = 0; kk < 2; kk++) {
            uint32_t a[4][4], b[2][4];
            #pragma unroll
            for (int mf = 0; mf < 4; mf++)
                ldsm_x4(a[mf][0], a[mf][1], a[mf][2], a[mf][3],
                        sbase + aoff[mf] + kk * 32);
            #pragma unroll
            for (int p = 0; p < 2; p++)
                ldsm_x4t(b[p][0], b[p][1], b[p][2], b[p][3],
                         sbase + boff[p] + kk * 16 * (B_PITCH * 2));
            #pragma unroll
            for (int mf = 0; mf < 4; mf++) {
                #pragma unroll
                for (int p = 0; p < 2; p++) {
                    mma16816(acc[mf][p * 2],     a[mf][0], a[mf][1], a[mf][2], a[mf][3],
                             b[p][0], b[p][1]);
                    mma16816(acc[mf][p * 2 + 1], a[mf][0], a[mf][1], a[mf][2], a[mf][3],
                             b[p][2], b[p][3]);
                }
            }
        }
        __syncthreads();
        if (s + 3 < NS) issue(s + 3);
    }

    // epilogue: fp32 float2 stores
    #pragma unroll
    for (int mf = 0; mf < 4; mf++) {
        int r0 = wm * 64 + mf * 16 + (lane >> 2);
        #pragma unroll
        for (int nf = 0; nf < 4; nf++) {
            int col = n0 + wn * 32 + nf * 8 + (lane & 3) * 2;
            if (r0 < mrem) {
                float2 v = { acc[mf][nf][0], acc[mf][nf][1] };
                *(float2*)(g_dout + (size_t)(rstart + r0) * H_DIM + col) = v;
            }
            if (r0 + 8 < mrem) {
                float2 v = { acc[mf][nf][2], acc[mf][nf][3] };
                *(float2*)(g_dout + (size_t)(rstart + r0 + 8) * H_DIM + col) = v;
            }
        }
    }
}

// ---------------- combine ----------------
__global__ void combine_kernel(float* __restrict__ out) {
    int t = blockIdx.x;
    int r0 = g_rowOf[t * K_TOP + 0], r1 = g_rowOf[t * K_TOP + 1];
    int r2 = g_rowOf[t * K_TOP + 2], r3 = g_rowOf[t * K_TOP + 3];
    float w0 = g_topk_w[t * K_TOP + 0], w1 = g_topk_w[t * K_TOP + 1];
    float w2 = g_topk_w[t * K_TOP + 2], w3 = g_topk_w[t * K_TOP + 3];
    const float4* d0 = (const float4*)(g_dout + (size_t)r0 * H_DIM);
    const float4* d1 = (const float4*)(g_dout + (size_t)r1 * H_DIM);
    const float4* d2 = (const float4*)(g_dout + (size_t)r2 * H_DIM);
    const float4* d3 = (const float4*)(g_dout + (size_t)r3 * H_DIM);
    float4* o = (float4*)(out + (size_t)t * H_DIM);
    for (int i = threadIdx.x; i < H_DIM / 4; i += 256) {
        float4 a = d0[i], b = d1[i], c = d2[i], d = d3[i];
        float4 r;
        r.x = w0 * a.x + w1 * b.x + w2 * c.x + w3 * d.x;
        r.y = w0 * a.y + w1 * b.y + w2 * c.y + w3 * d.y;
        r.z = w0 * a.z + w1 * b.z + w2 * c.z + w3 * d.z;
        r.w = w0 * a.w + w1 * b.w + w2 * c.w + w3 * d.w;
        o[i] = r;
    }
}

// ---------------- launch ----------------
extern "C" void kernel_launch(void* const* d_in, const int* in_sizes, int n_in,
                              void* d_out, int out_size) {
    const float* hidden = (const float*)d_in[0];
    const float* gate_w = (const float*)d_in[1];
    const float* w1     = (const float*)d_in[2];
    const float* w3     = (const float*)d_in[3];
    const float* w2     = (const float*)d_in[4];
    float* out = (float*)d_out;

    __half *w13, *w2h;
    cudaGetSymbolAddress((void**)&w13, g_w13);
    cudaGetSymbolAddress((void**)&w2h, g_w2h);

    cudaFuncSetAttribute(gemm1_kernel, cudaFuncAttributeMaxDynamicSharedMemorySize, SM_BYTES);
    cudaFuncSetAttribute(gemm2_kernel, cudaFuncAttributeMaxDynamicSharedMemorySize, SM_BYTES);

    init_kernel<<<1, 32>>>();
    interleave_convert<<<2048, 256>>>(w1, w3, w13, WELEM / 4);
    convert_kernel<<<2048, 256>>>(w2, w2h, WELEM / 4);
    router_kernel<<<T_TOK, 128>>>(hidden, gate_w);
    prefix_kernel<<<1, 32>>>();
    fill_kernel<<<E_NUM, 256>>>();
    gemm1_kernel<<<dim3(I_DIM / 64, T_TOK / 128, E_NUM), 256, SM_BYTES>>>();
    gemm2_kernel<<<dim3(H_DIM / 128, T_TOK / 128, E_NUM), 256, SM_BYTES>>>();
    combine_kernel<<<T_TOK, 256>>>(out);
}

// round 6
// speedup vs baseline: 4.0763x; 1.0044x over previous
#include <cuda_runtime.h>
#include <cuda_fp16.h>
#include <cstdint>
#include <cstddef>

#define T_TOK 2048
#define H_DIM 2048
#define I_DIM 1024
#define E_NUM 16
#define K_TOP 4
#define NPAIR (T_TOK * K_TOP)
#define WELEM (E_NUM * H_DIM * I_DIM)

// ---------------- static device scratch ----------------
__device__ int    g_topk_idx[T_TOK * K_TOP];
__device__ float  g_topk_w[T_TOK * K_TOP];
__device__ int    g_counts[E_NUM];
__device__ int    g_off[E_NUM];
__device__ int    g_srcTok[NPAIR];
__device__ int    g_rowOf[T_TOK * K_TOP];
__device__ __half g_hh[(size_t)T_TOK * H_DIM];       // fp16 hidden [T, H]
__device__ __half g_w13[(size_t)2 * WELEM];          // fp16 interleaved (w1,w3) [E][H][2I]
__device__ __half g_w2h[(size_t)WELEM];              // fp16 w2 [E][I][H]
__device__ __half g_act[(size_t)NPAIR * I_DIM];      // SwiGLU activations
__device__ float  g_dout[(size_t)NPAIR * H_DIM];     // per-pair down proj (unscaled)

// ---------------- helpers ----------------
__device__ __forceinline__ uint32_t smem_u32(const void* p) {
    return (uint32_t)__cvta_generic_to_shared(p);
}
__device__ __forceinline__ void cpa16(uint32_t s, const void* g) {
    asm volatile("cp.async.cg.shared.global [%0], [%1], 16;\n" :: "r"(s), "l"(g));
}
__device__ __forceinline__ void cp_commit() { asm volatile("cp.async.commit_group;\n"); }
__device__ __forceinline__ void cp_wait2()  { asm volatile("cp.async.wait_group 2;\n"); }
__device__ __forceinline__ void cp_wait1()  { asm volatile("cp.async.wait_group 1;\n"); }
__device__ __forceinline__ void cp_wait0()  { asm volatile("cp.async.wait_group 0;\n"); }

__device__ __forceinline__ void ldsm_x4(uint32_t& r0, uint32_t& r1, uint32_t& r2, uint32_t& r3,
                                        uint32_t addr) {
    asm volatile("ldmatrix.sync.aligned.m8n8.x4.shared.b16 {%0,%1,%2,%3}, [%4];"
                 : "=r"(r0), "=r"(r1), "=r"(r2), "=r"(r3) : "r"(addr));
}
__device__ __forceinline__ void ldsm_x4t(uint32_t& r0, uint32_t& r1, uint32_t& r2, uint32_t& r3,
                                         uint32_t addr) {
    asm volatile("ldmatrix.sync.aligned.m8n8.x4.trans.shared.b16 {%0,%1,%2,%3}, [%4];"
                 : "=r"(r0), "=r"(r1), "=r"(r2), "=r"(r3) : "r"(addr));
}
__device__ __forceinline__ void mma16816(float* d, uint32_t a0, uint32_t a1, uint32_t a2,
                                         uint32_t a3, uint32_t b0, uint32_t b1) {
    asm volatile(
        "mma.sync.aligned.m16n8k16.row.col.f32.f16.f16.f32 "
        "{%0,%1,%2,%3}, {%4,%5,%6,%7}, {%8,%9}, {%0,%1,%2,%3};"
        : "+f"(d[0]), "+f"(d[1]), "+f"(d[2]), "+f"(d[3])
        : "r"(a0), "r"(a1), "r"(a2), "r"(a3), "r"(b0), "r"(b1));
}

// ---------------- init ----------------
__global__ void init_kernel() {
    if (threadIdx.x < E_NUM) g_counts[threadIdx.x] = 0;
}

// ---------------- converts ----------------
__global__ void interleave_convert(const float* __restrict__ w1, const float* __restrict__ w3,
                                   __half* __restrict__ dst, int n4) {
    const float4* a4 = (const float4*)w1;
    const float4* b4 = (const float4*)w3;
    uint4* d4 = (uint4*)dst;
    for (int i = blockIdx.x * blockDim.x + threadIdx.x; i < n4; i += gridDim.x * blockDim.x) {
        float4 a = a4[i], b = b4[i];
        __half2 h0 = __floats2half2_rn(a.x, b.x);
        __half2 h1 = __floats2half2_rn(a.y, b.y);
        __half2 h2 = __floats2half2_rn(a.z, b.z);
        __half2 h3 = __floats2half2_rn(a.w, b.w);
        uint4 o;
        o.x = *(uint32_t*)&h0; o.y = *(uint32_t*)&h1;
        o.z = *(uint32_t*)&h2; o.w = *(uint32_t*)&h3;
        d4[i] = o;
    }
}
__global__ void convert_kernel(const float* __restrict__ src, __half* __restrict__ dst, int n4) {
    const float4* s4 = (const float4*)src;
    __half2* d2 = (__half2*)dst;
    for (int i = blockIdx.x * blockDim.x + threadIdx.x; i < n4; i += gridDim.x * blockDim.x) {
        float4 v = s4[i];
        d2[i * 2]     = __floats2half2_rn(v.x, v.y);
        d2[i * 2 + 1] = __floats2half2_rn(v.z, v.w);
    }
}

// ---------------- router: warp per token, fused hidden fp16 conversion ----------------
__global__ __launch_bounds__(256) void router_kernel(const float* __restrict__ hidden,
                                                     const float* __restrict__ gate_w) {
    int warp = threadIdx.x >> 5, lane = threadIdx.x & 31;
    int t = blockIdx.x * 8 + warp;
    const float4* hrow = (const float4*)(hidden + (size_t)t * H_DIM);
    __half2* hh = (__half2*)(g_hh + (size_t)t * H_DIM);
    float acc[E_NUM];
    #pragma unroll
    for (int e = 0; e < E_NUM; e++) acc[e] = 0.f;

    #pragma unroll 4
    for (int i = 0; i < 16; i++) {
        int idx = i * 32 + lane;              // float4 index in row (512 per row)
        float4 h = hrow[idx];
        hh[idx * 2]     = __floats2half2_rn(h.x, h.y);
        hh[idx * 2 + 1] = __floats2half2_rn(h.z, h.w);
        #pragma unroll
        for (int e = 0; e < E_NUM; e++) {
            float4 g = ((const float4*)(gate_w + (size_t)e * H_DIM))[idx];
            acc[e] += h.x * g.x + h.y * g.y + h.z * g.z + h.w * g.w;
        }
    }
    #pragma unroll
    for (int e = 0; e < E_NUM; e++)
        #pragma unroll
        for (int o = 16; o > 0; o >>= 1)
            acc[e] += __shfl_xor_sync(0xffffffffu, acc[e], o);

    if (lane == 0) {
        float mx = -1e30f;
        #pragma unroll
        for (int e = 0; e < E_NUM; e++) mx = fmaxf(mx, acc[e]);
        float pr[E_NUM];
        #pragma unroll
        for (int e = 0; e < E_NUM; e++) pr[e] = __expf(acc[e] - mx);
        int idx[K_TOP]; float w[K_TOP];
        #pragma unroll
        for (int k = 0; k < K_TOP; k++) {
            float bv = -1.f; int bi = 0;
            #pragma unroll
            for (int e = 0; e < E_NUM; e++) {
                bool used = false;
                for (int kk = 0; kk < k; kk++) if (idx[kk] == e) used = true;
                if (!used && pr[e] > bv) { bv = pr[e]; bi = e; }
            }
            idx[k] = bi; w[k] = bv;
        }
        float inv = 1.f / (w[0] + w[1] + w[2] + w[3]);
        #pragma unroll
        for (int k = 0; k < K_TOP; k++) {
            g_topk_idx[t * K_TOP + k] = idx[k];
            g_topk_w[t * K_TOP + k]   = w[k] * inv;
            atomicAdd(&g_counts[idx[k]], 1);
        }
    }
}

// ---------------- fill (prefix inlined) ----------------
__global__ void fill_kernel() {
    int e = blockIdx.x;
    int start = 0;
    for (int i = 0; i < e; i++) start += g_counts[i];
    __shared__ int s_counter, s_prefix[8], s_wsum[8];
    int tid = threadIdx.x, lane = tid & 31, wid = tid >> 5;
    if (tid == 0) { g_off[e] = start; s_counter = 0; }
    __syncthreads();
    for (int base = 0; base < T_TOK; base += 256) {
        int t = base + tid;
        int myk = -1;
        #pragma unroll
        for (int k = 0; k < K_TOP; k++) if (g_topk_idx[t * K_TOP + k] == e) myk = k;
        unsigned bal = __ballot_sync(0xffffffffu, myk >= 0);
        if (lane == 0) s_wsum[wid] = __popc(bal);
        __syncthreads();
        if (tid == 0) {
            int acc = s_counter;
            for (int w = 0; w < 8; w++) { s_prefix[w] = acc; acc += s_wsum[w]; }
            s_counter = acc;
        }
        __syncthreads();
        if (myk >= 0) {
            int j = s_prefix[wid] + __popc(bal & ((1u << lane) - 1));
            int r = start + j;
            g_srcTok[r] = t;
            g_rowOf[t * K_TOP + myk] = r;
        }
        __syncthreads();
    }
}

// ---------------- GEMM smem layout: 4-stage ring ----------------
#define A_PITCH 40
#define B_PITCH 136
#define A_BYTES (128 * A_PITCH * 2)
#define STAGE_BYTES (A_BYTES + 32 * B_PITCH * 2)
#define SM_STAGE0 1024
#define N_STAGES 4
#define SM_BYTES (SM_STAGE0 + N_STAGES * STAGE_BYTES)

// ---------------- GEMM1: [128 rows] x K=2048 -> 64 I-cols (interleaved pairs) ----------------
__global__ __launch_bounds__(256, 2) void gemm1_kernel() {
    int e = blockIdx.z;
    int M_e = g_counts[e];
    int mbase = blockIdx.y * 128;
    if (mbase >= M_e) return;
    int n0o = blockIdx.x * 64;
    int rstart = g_off[e] + mbase;
    int mrem = M_e - mbase; if (mrem > 128) mrem = 128;

    extern __shared__ __align__(16) char smem[];
    int* rows_s = (int*)smem;
    uint32_t sb = smem_u32(smem);
    int tid = threadIdx.x, lane = tid & 31;
    int warp = tid >> 5, wm = warp >> 2, wn = warp & 3;

    if (tid < 128) rows_s[tid] = (tid < mrem) ? g_srcTok[rstart + tid] : 0;
    __syncthreads();

    const __half* wb = g_w13 + (size_t)e * H_DIM * (2 * I_DIM) + 2 * n0o;

    int am = tid >> 2, aseg = tid & 3;
    const __half* asrc0 = g_hh + (size_t)rows_s[am] * H_DIM + aseg * 8;
    const __half* asrc1 = g_hh + (size_t)rows_s[am + 64] * H_DIM + aseg * 8;
    uint32_t adst0 = sb + SM_STAGE0 + am * (A_PITCH * 2) + aseg * 16;
    uint32_t adst1 = sb + SM_STAGE0 + (am + 64) * (A_PITCH * 2) + aseg * 16;
    int bk = tid >> 4, bseg = tid & 15;
    const __half* bsrc0 = wb + (size_t)bk * (2 * I_DIM) + bseg * 8;
    const __half* bsrc1 = wb + (size_t)(bk + 16) * (2 * I_DIM) + bseg * 8;
    uint32_t bdst0 = sb + SM_STAGE0 + A_BYTES + bk * (B_PITCH * 2) + bseg * 16;
    uint32_t bdst1 = sb + SM_STAGE0 + A_BYTES + (bk + 16) * (B_PITCH * 2) + bseg * 16;

    uint32_t aoff[4], boff[2];
    #pragma unroll
    for (int mf = 0; mf < 4; mf++)
        aoff[mf] = (wm * 64 + mf * 16 + (lane & 15)) * (A_PITCH * 2) + (lane >> 4) * 16;
    #pragma unroll
    for (int p = 0; p < 2; p++)
        boff[p] = A_BYTES + ((lane & 7) + 8 * ((lane >> 3) & 1)) * (B_PITCH * 2)
                + (wn * 32 + p * 16 + 8 * (lane >> 4)) * 2;

    float acc[4][4][4];
    #pragma unroll
    for (int i = 0; i < 4; i++)
        #pragma unroll
        for (int j = 0; j < 4; j++)
            #pragma unroll
            for (int r = 0; r < 4; r++) acc[i][j][r] = 0.f;

    auto issue = [&](int s) {
        uint32_t so = (uint32_t)((s & 3) * STAGE_BYTES);
        size_t ka = (size_t)s * 32;
        size_t kb = (size_t)s * 32 * (2 * I_DIM);
        cpa16(adst0 + so, asrc0 + ka);
        cpa16(adst1 + so, asrc1 + ka);
        cpa16(bdst0 + so, bsrc0 + kb);
        cpa16(bdst1 + so, bsrc1 + kb);
        cp_commit();
    };

    const int NS = H_DIM / 32;   // 64
    issue(0); issue(1); issue(2);
    for (int s = 0; s < NS; s++) {
        int w = NS - 1 - s;
        if (w >= 2) cp_wait2(); else if (w == 1) cp_wait1(); else cp_wait0();
        __syncthreads();
        uint32_t sbase = sb + SM_STAGE0 + (uint32_t)((s & 3) * STAGE_BYTES);
        #pragma unroll
        for (int kk = 0; kk < 2; kk++) {
            uint32_t a[4][4], b[2][4];
            #pragma unroll
            for (int mf = 0; mf < 4; mf++)
                ldsm_x4(a[mf][0], a[mf][1], a[mf][2], a[mf][3],
                        sbase + aoff[mf] + kk * 32);
            #pragma unroll
            for (int p = 0; p < 2; p++)
                ldsm_x4t(b[p][0], b[p][1], b[p][2], b[p][3],
                         sbase + boff[p] + kk * 16 * (B_PITCH * 2));
            #pragma unroll
            for (int mf = 0; mf < 4; mf++) {
                #pragma unroll
                for (int p = 0; p < 2; p++) {
                    mma16816(acc[mf][p * 2],     a[mf][0], a[mf][1], a[mf][2], a[mf][3],
                             b[p][0], b[p][1]);
                    mma16816(acc[mf][p * 2 + 1], a[mf][0], a[mf][1], a[mf][2], a[mf][3],
                             b[p][2], b[p][3]);
                }
            }
        }
        if (s + 3 < NS) issue(s + 3);   // overwrites buffer of stage s-1; all warps past top sync
    }

    #pragma unroll
    for (int mf = 0; mf < 4; mf++) {
        int r0 = wm * 64 + mf * 16 + (lane >> 2);
        #pragma unroll
        for (int nf = 0; nf < 4; nf++) {
            int col = n0o + wn * 16 + nf * 4 + (lane & 3);
            float x0 = acc[mf][nf][0], y0 = acc[mf][nf][1];
            float x1 = acc[mf][nf][2], y1 = acc[mf][nf][3];
            float v0 = x0 / (1.0f + __expf(-x0)) * y0;
            float v1 = x1 / (1.0f + __expf(-x1)) * y1;
            if (r0 < mrem)     g_act[(size_t)(rstart + r0) * I_DIM + col]     = __float2half(v0);
            if (r0 + 8 < mrem) g_act[(size_t)(rstart + r0 + 8) * I_DIM + col] = __float2half(v1);
        }
    }
}

// ---------------- GEMM2: dout[128, 128H] = act[128, I] x w2h ----------------
__global__ __launch_bounds__(256, 2) void gemm2_kernel() {
    int e = blockIdx.z;
    int M_e = g_counts[e];
    int mbase = blockIdx.y * 128;
    if (mbase >= M_e) return;
    int n0 = blockIdx.x * 128;
    int rstart = g_off[e] + mbase;
    int mrem = M_e - mbase; if (mrem > 128) mrem = 128;

    extern __shared__ __align__(16) char smem[];
    uint32_t sb = smem_u32(smem);
    int tid = threadIdx.x, lane = tid & 31;
    int warp = tid >> 5, wm = warp >> 2, wn = warp & 3;

    const __half* wb = g_w2h + (size_t)e * I_DIM * H_DIM + n0;

    int am = tid >> 2, aseg = tid & 3;
    int ar0 = rstart + am;      if (ar0 >= NPAIR) ar0 = NPAIR - 1;
    int ar1 = rstart + am + 64; if (ar1 >= NPAIR) ar1 = NPAIR - 1;
    const __half* asrc0 = g_act + (size_t)ar0 * I_DIM + aseg * 8;
    const __half* asrc1 = g_act + (size_t)ar1 * I_DIM + aseg * 8;
    uint32_t adst0 = sb + SM_STAGE0 + am * (A_PITCH * 2) + aseg * 16;
    uint32_t adst1 = sb + SM_STAGE0 + (am + 64) * (A_PITCH * 2) + aseg * 16;
    int bk = tid >> 4, bseg = tid & 15;
    const __half* bsrc0 = wb + (size_t)bk * H_DIM + bseg * 8;
    const __half* bsrc1 = wb + (size_t)(bk + 16) * H_DIM + bseg * 8;
    uint32_t bdst0 = sb + SM_STAGE0 + A_BYTES + bk * (B_PITCH * 2) + bseg * 16;
    uint32_t bdst1 = sb + SM_STAGE0 + A_BYTES + (bk + 16) * (B_PITCH * 2) + bseg * 16;

    uint32_t aoff[4], boff[2];
    #pragma unroll
    for (int mf = 0; mf < 4; mf++)
        aoff[mf] = (wm * 64 + mf * 16 + (lane & 15)) * (A_PITCH * 2) + (lane >> 4) * 16;
    #pragma unroll
    for (int p = 0; p < 2; p++)
        boff[p] = A_BYTES + ((lane & 7) + 8 * ((lane >> 3) & 1)) * (B_PITCH * 2)
                + (wn * 32 + p * 16 + 8 * (lane >> 4)) * 2;

    float acc[4][4][4];
    #pragma unroll
    for (int i = 0; i < 4; i++)
        #pragma unroll
        for (int j = 0; j < 4; j++)
            #pragma unroll
            for (int r = 0; r < 4; r++) acc[i][j][r] = 0.f;

    auto issue = [&](int s) {
        uint32_t so = (uint32_t)((s & 3) * STAGE_BYTES);
        size_t ka = (size_t)s * 32;
        size_t kb = (size_t)s * 32 * H_DIM;
        cpa16(adst0 + so, asrc0 + ka);
        cpa16(adst1 + so, asrc1 + ka);
        cpa16(bdst0 + so, bsrc0 + kb);
        cpa16(bdst1 + so, bsrc1 + kb);
        cp_commit();
    };

    const int NS = I_DIM / 32;   // 32
    issue(0); issue(1); issue(2);
    for (int s = 0; s < NS; s++) {
        int w = NS - 1 - s;
        if (w >= 2) cp_wait2(); else if (w == 1) cp_wait1(); else cp_wait0();
        __syncthreads();
        uint32_t sbase = sb + SM_STAGE0 + (uint32_t)((s & 3) * STAGE_BYTES);
        #pragma unroll
        for (int kk = 0; kk < 2; kk++) {
            uint32_t a[4][4], b[2][4];
            #pragma unroll
            for (int mf = 0; mf < 4; mf++)
                ldsm_x4(a[mf][0], a[mf][1], a[mf][2], a[mf][3],
                        sbase + aoff[mf] + kk * 32);
            #pragma unroll
            for (int p = 0; p < 2; p++)
                ldsm_x4t(b[p][0], b[p][1], b[p][2], b[p][3],
                         sbase + boff[p] + kk * 16 * (B_PITCH * 2));
            #pragma unroll
            for (int mf = 0; mf < 4; mf++) {
                #pragma unroll
                for (int p = 0; p < 2; p++) {
                    mma16816(acc[mf][p * 2],     a[mf][0], a[mf][1], a[mf][2], a[mf][3],
                             b[p][0], b[p][1]);
                    mma16816(acc[mf][p * 2 + 1], a[mf][0], a[mf][1], a[mf][2], a[mf][3],
                             b[p][2], b[p][3]);
                }
            }
        }
        if (s + 3 < NS) issue(s + 3);
    }

    #pragma unroll
    for (int mf = 0; mf < 4; mf++) {
        int r0 = wm * 64 + mf * 16 + (lane >> 2);
        #pragma unroll
        for (int nf = 0; nf < 4; nf++) {
            int col = n0 + wn * 32 + nf * 8 + (lane & 3) * 2;
            if (r0 < mrem) {
                float2 v = { acc[mf][nf][0], acc[mf][nf][1] };
                *(float2*)(g_dout + (size_t)(rstart + r0) * H_DIM + col) = v;
            }
            if (r0 + 8 < mrem) {
                float2 v = { acc[mf][nf][2], acc[mf][nf][3] };
                *(float2*)(g_dout + (size_t)(rstart + r0 + 8) * H_DIM + col) = v;
            }
        }
    }
}

// ---------------- combine ----------------
__global__ void combine_kernel(float* __restrict__ out) {
    int t = blockIdx.x;
    int r0 = g_rowOf[t * K_TOP + 0], r1 = g_rowOf[t * K_TOP + 1];
    int r2 = g_rowOf[t * K_TOP + 2], r3 = g_rowOf[t * K_TOP + 3];
    float w0 = g_topk_w[t * K_TOP + 0], w1 = g_topk_w[t * K_TOP + 1];
    float w2 = g_topk_w[t * K_TOP + 2], w3 = g_topk_w[t * K_TOP + 3];
    const float4* d0 = (const float4*)(g_dout + (size_t)r0 * H_DIM);
    const float4* d1 = (const float4*)(g_dout + (size_t)r1 * H_DIM);
    const float4* d2 = (const float4*)(g_dout + (size_t)r2 * H_DIM);
    const float4* d3 = (const float4*)(g_dout + (size_t)r3 * H_DIM);
    float4* o = (float4*)(out + (size_t)t * H_DIM);
    for (int i = threadIdx.x; i < H_DIM / 4; i += 256) {
        float4 a = d0[i], b = d1[i], c = d2[i], d = d3[i];
        float4 r;
        r.x = w0 * a.x + w1 * b.x + w2 * c.x + w3 * d.x;
        r.y = w0 * a.y + w1 * b.y + w2 * c.y + w3 * d.y;
        r.z = w0 * a.z + w1 * b.z + w2 * c.z + w3 * d.z;
        r.w = w0 * a.w + w1 * b.w + w2 * c.w + w3 * d.w;
        o[i] = r;
    }
}

// ---------------- launch ----------------
extern "C" void kernel_launch(void* const* d_in, const int* in_sizes, int n_in,
                              void* d_out, int out_size) {
    const float* hidden = (const float*)d_in[0];
    const float* gate_w = (const float*)d_in[1];
    const float* w1     = (const float*)d_in[2];
    const float* w3     = (const float*)d_in[3];
    const float* w2     = (const float*)d_in[4];
    float* out = (float*)d_out;

    __half *w13, *w2h;
    cudaGetSymbolAddress((void**)&w13, g_w13);
    cudaGetSymbolAddress((void**)&w2h, g_w2h);

    cudaFuncSetAttribute(gemm1_kernel, cudaFuncAttributeMaxDynamicSharedMemorySize, SM_BYTES);
    cudaFuncSetAttribute(gemm2_kernel, cudaFuncAttributeMaxDynamicSharedMemorySize, SM_BYTES);

    init_kernel<<<1, 32>>>();                                    // 1
    interleave_convert<<<2048, 256>>>(w1, w3, w13, WELEM / 4);   // 2
    convert_kernel<<<2048, 256>>>(w2, w2h, WELEM / 4);           // 3
    router_kernel<<<T_TOK / 8, 256>>>(hidden, gate_w);           // 4
    fill_kernel<<<E_NUM, 256>>>();                               // 5
    gemm1_kernel<<<dim3(I_DIM / 64, T_TOK / 128, E_NUM), 256, SM_BYTES>>>();  // 6 (profiled)
    gemm2_kernel<<<dim3(H_DIM / 128, T_TOK / 128, E_NUM), 256, SM_BYTES>>>(); // 7
    combine_kernel<<<T_TOK, 256>>>(out);                         // 8
}

// round 7
// speedup vs baseline: 4.4932x; 1.1023x over previous
#include <cuda_runtime.h>
#include <cuda_fp16.h>
#include <cstdint>
#include <cstddef>

#define T_TOK 2048
#define H_DIM 2048
#define I_DIM 1024
#define E_NUM 16
#define K_TOP 4
#define NPAIR (T_TOK * K_TOP)

// ---------------- static device scratch ----------------
__device__ int    g_topk_idx[T_TOK * K_TOP];
__device__ float  g_topk_w[T_TOK * K_TOP];
__device__ int    g_counts[E_NUM];
__device__ int    g_off[E_NUM];
__device__ int    g_srcTok[NPAIR];
__device__ int    g_rowOf[T_TOK * K_TOP];
__device__ __half g_hh[(size_t)T_TOK * H_DIM];       // fp16 hidden [T, H]
__device__ __half g_act[(size_t)NPAIR * I_DIM];      // SwiGLU activations
__device__ float  g_dout[(size_t)NPAIR * H_DIM];     // per-pair down proj (unscaled)

// ---------------- helpers ----------------
__device__ __forceinline__ uint32_t smem_u32(const void* p) {
    return (uint32_t)__cvta_generic_to_shared(p);
}
__device__ __forceinline__ void cpa16(uint32_t s, const void* g) {
    asm volatile("cp.async.cg.shared.global [%0], [%1], 16;\n" :: "r"(s), "l"(g));
}
__device__ __forceinline__ void cp_commit() { asm volatile("cp.async.commit_group;\n"); }
__device__ __forceinline__ void cp_wait2()  { asm volatile("cp.async.wait_group 2;\n"); }
__device__ __forceinline__ void cp_wait1()  { asm volatile("cp.async.wait_group 1;\n"); }
__device__ __forceinline__ void cp_wait0()  { asm volatile("cp.async.wait_group 0;\n"); }

__device__ __forceinline__ void ldsm_x4(uint32_t& r0, uint32_t& r1, uint32_t& r2, uint32_t& r3,
                                        uint32_t addr) {
    asm volatile("ldmatrix.sync.aligned.m8n8.x4.shared.b16 {%0,%1,%2,%3}, [%4];"
                 : "=r"(r0), "=r"(r1), "=r"(r2), "=r"(r3) : "r"(addr));
}
__device__ __forceinline__ void ldsm_x4t(uint32_t& r0, uint32_t& r1, uint32_t& r2, uint32_t& r3,
                                         uint32_t addr) {
    asm volatile("ldmatrix.sync.aligned.m8n8.x4.trans.shared.b16 {%0,%1,%2,%3}, [%4];"
                 : "=r"(r0), "=r"(r1), "=r"(r2), "=r"(r3) : "r"(addr));
}
__device__ __forceinline__ void mma16816(float* d, uint32_t a0, uint32_t a1, uint32_t a2,
                                         uint32_t a3, uint32_t b0, uint32_t b1) {
    asm volatile(
        "mma.sync.aligned.m16n8k16.row.col.f32.f16.f16.f32 "
        "{%0,%1,%2,%3}, {%4,%5,%6,%7}, {%8,%9}, {%0,%1,%2,%3};"
        : "+f"(d[0]), "+f"(d[1]), "+f"(d[2]), "+f"(d[3])
        : "r"(a0), "r"(a1), "r"(a2), "r"(a3), "r"(b0), "r"(b1));
}
__device__ __forceinline__ uint4 pack8_interleave(float4 a, float4 b) {
    __half2 h0 = __floats2half2_rn(a.x, b.x);
    __half2 h1 = __floats2half2_rn(a.y, b.y);
    __half2 h2 = __floats2half2_rn(a.z, b.z);
    __half2 h3 = __floats2half2_rn(a.w, b.w);
    uint4 o;
    o.x = *(uint32_t*)&h0; o.y = *(uint32_t*)&h1;
    o.z = *(uint32_t*)&h2; o.w = *(uint32_t*)&h3;
    return o;
}
__device__ __forceinline__ uint4 pack8_linear(float4 a, float4 b) {
    __half2 h0 = __floats2half2_rn(a.x, a.y);
    __half2 h1 = __floats2half2_rn(a.z, a.w);
    __half2 h2 = __floats2half2_rn(b.x, b.y);
    __half2 h3 = __floats2half2_rn(b.z, b.w);
    uint4 o;
    o.x = *(uint32_t*)&h0; o.y = *(uint32_t*)&h1;
    o.z = *(uint32_t*)&h2; o.w = *(uint32_t*)&h3;
    return o;
}

// ---------------- init ----------------
__global__ void init_kernel() {
    if (threadIdx.x < E_NUM) g_counts[threadIdx.x] = 0;
}

// ---------------- router: warp per token (4 tokens / 128-thread block) ----------------
__global__ __launch_bounds__(128) void router_kernel(const float* __restrict__ hidden,
                                                     const float* __restrict__ gate_w) {
    int warp = threadIdx.x >> 5, lane = threadIdx.x & 31;
    int t = blockIdx.x * 4 + warp;
    const float4* hrow = (const float4*)(hidden + (size_t)t * H_DIM);
    __half2* hh = (__half2*)(g_hh + (size_t)t * H_DIM);
    float acc[E_NUM];
    #pragma unroll
    for (int e = 0; e < E_NUM; e++) acc[e] = 0.f;

    #pragma unroll 4
    for (int i = 0; i < 16; i++) {
        int idx = i * 32 + lane;
        float4 h = hrow[idx];
        hh[idx * 2]     = __floats2half2_rn(h.x, h.y);
        hh[idx * 2 + 1] = __floats2half2_rn(h.z, h.w);
        #pragma unroll
        for (int e = 0; e < E_NUM; e++) {
            float4 g = ((const float4*)(gate_w + (size_t)e * H_DIM))[idx];
            acc[e] += h.x * g.x + h.y * g.y + h.z * g.z + h.w * g.w;
        }
    }
    #pragma unroll
    for (int e = 0; e < E_NUM; e++)
        #pragma unroll
        for (int o = 16; o > 0; o >>= 1)
            acc[e] += __shfl_xor_sync(0xffffffffu, acc[e], o);

    if (lane == 0) {
        float mx = -1e30f;
        #pragma unroll
        for (int e = 0; e < E_NUM; e++) mx = fmaxf(mx, acc[e]);
        float pr[E_NUM];
        #pragma unroll
        for (int e = 0; e < E_NUM; e++) pr[e] = __expf(acc[e] - mx);
        int idx[K_TOP]; float w[K_TOP];
        #pragma unroll
        for (int k = 0; k < K_TOP; k++) {
            float bv = -1.f; int bi = 0;
            #pragma unroll
            for (int e = 0; e < E_NUM; e++) {
                bool used = false;
                for (int kk = 0; kk < k; kk++) if (idx[kk] == e) used = true;
                if (!used && pr[e] > bv) { bv = pr[e]; bi = e; }
            }
            idx[k] = bi; w[k] = bv;
        }
        float inv = 1.f / (w[0] + w[1] + w[2] + w[3]);
        #pragma unroll
        for (int k = 0; k < K_TOP; k++) {
            g_topk_idx[t * K_TOP + k] = idx[k];
            g_topk_w[t * K_TOP + k]   = w[k] * inv;
            atomicAdd(&g_counts[idx[k]], 1);
        }
    }
}

// ---------------- fill (prefix inlined) ----------------
__global__ void fill_kernel() {
    int e = blockIdx.x;
    int start = 0;
    for (int i = 0; i < e; i++) start += g_counts[i];
    __shared__ int s_counter, s_prefix[8], s_wsum[8];
    int tid = threadIdx.x, lane = tid & 31, wid = tid >> 5;
    if (tid == 0) { g_off[e] = start; s_counter = 0; }
    __syncthreads();
    for (int base = 0; base < T_TOK; base += 256) {
        int t = base + tid;
        int myk = -1;
        #pragma unroll
        for (int k = 0; k < K_TOP; k++) if (g_topk_idx[t * K_TOP + k] == e) myk = k;
        unsigned bal = __ballot_sync(0xffffffffu, myk >= 0);
        if (lane == 0) s_wsum[wid] = __popc(bal);
        __syncthreads();
        if (tid == 0) {
            int acc = s_counter;
            for (int w = 0; w < 8; w++) { s_prefix[w] = acc; acc += s_wsum[w]; }
            s_counter = acc;
        }
        __syncthreads();
        if (myk >= 0) {
            int j = s_prefix[wid] + __popc(bal & ((1u << lane) - 1));
            int r = start + j;
            g_srcTok[r] = t;
            g_rowOf[t * K_TOP + myk] = r;
        }
        __syncthreads();
    }
}

// ---------------- GEMM smem layout: 4-stage ring ----------------
#define A_PITCH 40
#define B_PITCH 136
#define A_BYTES (128 * A_PITCH * 2)
#define STAGE_BYTES (A_BYTES + 32 * B_PITCH * 2)
#define SM_STAGE0 1024
#define N_STAGES 4
#define SM_BYTES (SM_STAGE0 + N_STAGES * STAGE_BYTES)

// ---------------- GEMM1: [128 rows] x K=2048 -> 64 I-cols; B = fused-convert fp32 w1/w3 ------
__global__ __launch_bounds__(256, 2) void gemm1_kernel(const float* __restrict__ w1,
                                                       const float* __restrict__ w3) {
    int e = blockIdx.z;
    int M_e = g_counts[e];
    int mbase = blockIdx.y * 128;
    if (mbase >= M_e) return;
    int n0o = blockIdx.x * 64;
    int rstart = g_off[e] + mbase;
    int mrem = M_e - mbase; if (mrem > 128) mrem = 128;

    extern __shared__ __align__(16) char smem[];
    int* rows_s = (int*)smem;
    uint32_t sb = smem_u32(smem);
    int tid = threadIdx.x, lane = tid & 31;
    int warp = tid >> 5, wm = warp >> 2, wn = warp & 3;

    if (tid < 128) rows_s[tid] = (tid < mrem) ? g_srcTok[rstart + tid] : 0;
    __syncthreads();

    // A cp.async setup (fp16 hidden)
    int am = tid >> 2, aseg = tid & 3;
    const __half* asrc0 = g_hh + (size_t)rows_s[am] * H_DIM + aseg * 8;
    const __half* asrc1 = g_hh + (size_t)rows_s[am + 64] * H_DIM + aseg * 8;
    uint32_t adst0 = sb + SM_STAGE0 + am * (A_PITCH * 2) + aseg * 16;
    uint32_t adst1 = sb + SM_STAGE0 + (am + 64) * (A_PITCH * 2) + aseg * 16;

    // B fp32 direct-load setup: slots (k, i4); 2 per thread
    const float* b1p[2]; const float* b3p[2]; uint32_t bofs[2];
    #pragma unroll
    for (int p = 0; p < 2; p++) {
        int slot = tid + p * 256;
        int k = slot >> 4, i4 = slot & 15;
        size_t o = ((size_t)e * H_DIM + k) * I_DIM + n0o + i4 * 4;
        b1p[p] = w1 + o;
        b3p[p] = w3 + o;
        bofs[p] = A_BYTES + (uint32_t)(k * (B_PITCH * 2) + i4 * 16);
    }

    uint32_t aoff[4], boff[2];
    #pragma unroll
    for (int mf = 0; mf < 4; mf++)
        aoff[mf] = (wm * 64 + mf * 16 + (lane & 15)) * (A_PITCH * 2) + (lane >> 4) * 16;
    #pragma unroll
    for (int p = 0; p < 2; p++)
        boff[p] = A_BYTES + ((lane & 7) + 8 * ((lane >> 3) & 1)) * (B_PITCH * 2)
                + (wn * 32 + p * 16 + 8 * (lane >> 4)) * 2;

    float acc[4][4][4];
    #pragma unroll
    for (int i = 0; i < 4; i++)
        #pragma unroll
        for (int j = 0; j < 4; j++)
            #pragma unroll
            for (int r = 0; r < 4; r++) acc[i][j][r] = 0.f;

    auto issueA = [&](int s) {
        uint32_t so = (uint32_t)((s & 3) * STAGE_BYTES);
        size_t ka = (size_t)s * 32;
        cpa16(adst0 + so, asrc0 + ka);
        cpa16(adst1 + so, asrc1 + ka);
        cp_commit();
    };
    auto stsB = [&](int s, const float4* f1, const float4* f3) {
        uint32_t so = sb + SM_STAGE0 + (uint32_t)((s & 3) * STAGE_BYTES);
        #pragma unroll
        for (int p = 0; p < 2; p++)
            *(uint4*)(smem + (so - sb) + bofs[p]) = pack8_interleave(f1[p], f3[p]);
    };

    const int NS = H_DIM / 32;   // 64
    // prologue: A stages 0..2, B stages 0..2 (serial ldg->sts)
    issueA(0); issueA(1); issueA(2);
    #pragma unroll
    for (int s = 0; s < 3; s++) {
        float4 f1[2], f3[2];
        size_t kb = (size_t)s * 32 * I_DIM;
        #pragma unroll
        for (int p = 0; p < 2; p++) { f1[p] = *(const float4*)(b1p[p] + kb);
                                      f3[p] = *(const float4*)(b3p[p] + kb); }
        stsB(s, f1, f3);
    }

    for (int s = 0; s < NS; s++) {
        float4 f1[2], f3[2];
        bool pre = (s + 3 < NS);
        if (pre) {
            size_t kb = (size_t)(s + 3) * 32 * I_DIM;
            #pragma unroll
            for (int p = 0; p < 2; p++) { f1[p] = *(const float4*)(b1p[p] + kb);
                                          f3[p] = *(const float4*)(b3p[p] + kb); }
        }
        int w = NS - 1 - s;
        if (w >= 2) cp_wait2(); else if (w == 1) cp_wait1(); else cp_wait0();
        __syncthreads();
        uint32_t sbase = sb + SM_STAGE0 + (uint32_t)((s & 3) * STAGE_BYTES);
        #pragma unroll
        for (int kk = 0; kk < 2; kk++) {
            uint32_t a[4][4], b[2][4];
            #pragma unroll
            for (int mf = 0; mf < 4; mf++)
                ldsm_x4(a[mf][0], a[mf][1], a[mf][2], a[mf][3],
                        sbase + aoff[mf] + kk * 32);
            #pragma unroll
            for (int p = 0; p < 2; p++)
                ldsm_x4t(b[p][0], b[p][1], b[p][2], b[p][3],
                         sbase + boff[p] + kk * 16 * (B_PITCH * 2));
            #pragma unroll
            for (int mf = 0; mf < 4; mf++) {
                #pragma unroll
                for (int p = 0; p < 2; p++) {
                    mma16816(acc[mf][p * 2],     a[mf][0], a[mf][1], a[mf][2], a[mf][3],
                             b[p][0], b[p][1]);
                    mma16816(acc[mf][p * 2 + 1], a[mf][0], a[mf][1], a[mf][2], a[mf][3],
                             b[p][2], b[p][3]);
                }
            }
        }
        if (pre) { issueA(s + 3); stsB(s + 3, f1, f3); }
    }

    #pragma unroll
    for (int mf = 0; mf < 4; mf++) {
        int r0 = wm * 64 + mf * 16 + (lane >> 2);
        #pragma unroll
        for (int nf = 0; nf < 4; nf++) {
            int col = n0o + wn * 16 + nf * 4 + (lane & 3);
            float x0 = acc[mf][nf][0], y0 = acc[mf][nf][1];
            float x1 = acc[mf][nf][2], y1 = acc[mf][nf][3];
            float v0 = x0 / (1.0f + __expf(-x0)) * y0;
            float v1 = x1 / (1.0f + __expf(-x1)) * y1;
            if (r0 < mrem)     g_act[(size_t)(rstart + r0) * I_DIM + col]     = __float2half(v0);
            if (r0 + 8 < mrem) g_act[(size_t)(rstart + r0 + 8) * I_DIM + col] = __float2half(v1);
        }
    }
}

// ---------------- GEMM2: dout[128, 128H] = act[128, I] x w2 (fused fp32 convert) -----------
__global__ __launch_bounds__(256, 2) void gemm2_kernel(const float* __restrict__ w2) {
    int e = blockIdx.z;
    int M_e = g_counts[e];
    int mbase = blockIdx.y * 128;
    if (mbase >= M_e) return;
    int n0 = blockIdx.x * 128;
    int rstart = g_off[e] + mbase;
    int mrem = M_e - mbase; if (mrem > 128) mrem = 128;

    extern __shared__ __align__(16) char smem[];
    uint32_t sb = smem_u32(smem);
    int tid = threadIdx.x, lane = tid & 31;
    int warp = tid >> 5, wm = warp >> 2, wn = warp & 3;

    int am = tid >> 2, aseg = tid & 3;
    int ar0 = rstart + am;      if (ar0 >= NPAIR) ar0 = NPAIR - 1;
    int ar1 = rstart + am + 64; if (ar1 >= NPAIR) ar1 = NPAIR - 1;
    const __half* asrc0 = g_act + (size_t)ar0 * I_DIM + aseg * 8;
    const __half* asrc1 = g_act + (size_t)ar1 * I_DIM + aseg * 8;
    uint32_t adst0 = sb + SM_STAGE0 + am * (A_PITCH * 2) + aseg * 16;
    uint32_t adst1 = sb + SM_STAGE0 + (am + 64) * (A_PITCH * 2) + aseg * 16;

    // B fp32 slots: (k, n8), 2 per thread
    const float* bp[2]; uint32_t bofs[2];
    #pragma unroll
    for (int p = 0; p < 2; p++) {
        int slot = tid + p * 256;
        int k = slot >> 4, n8 = slot & 15;
        bp[p] = w2 + ((size_t)e * I_DIM + k) * H_DIM + n0 + n8 * 8;
        bofs[p] = A_BYTES + (uint32_t)(k * (B_PITCH * 2) + n8 * 16);
    }

    uint32_t aoff[4], boff[2];
    #pragma unroll
    for (int mf = 0; mf < 4; mf++)
        aoff[mf] = (wm * 64 + mf * 16 + (lane & 15)) * (A_PITCH * 2) + (lane >> 4) * 16;
    #pragma unroll
    for (int p = 0; p < 2; p++)
        boff[p] = A_BYTES + ((lane & 7) + 8 * ((lane >> 3) & 1)) * (B_PITCH * 2)
                + (wn * 32 + p * 16 + 8 * (lane >> 4)) * 2;

    float acc[4][4][4];
    #pragma unroll
    for (int i = 0; i < 4; i++)
        #pragma unroll
        for (int j = 0; j < 4; j++)
            #pragma unroll
            for (int r = 0; r < 4; r++) acc[i][j][r] = 0.f;

    auto issueA = [&](int s) {
        uint32_t so = (uint32_t)((s & 3) * STAGE_BYTES);
        size_t ka = (size_t)s * 32;
        cpa16(adst0 + so, asrc0 + ka);
        cpa16(adst1 + so, asrc1 + ka);
        cp_commit();
    };
    auto stsB = [&](int s, const float4* lo, const float4* hi) {
        uint32_t so = (uint32_t)((s & 3) * STAGE_BYTES);
        #pragma unroll
        for (int p = 0; p < 2; p++)
            *(uint4*)(smem + SM_STAGE0 + so + bofs[p]) = pack8_linear(lo[p], hi[p]);
    };

    const int NS = I_DIM / 32;   // 32
    issueA(0); issueA(1); issueA(2);
    #pragma unroll
    for (int s = 0; s < 3; s++) {
        float4 lo[2], hi[2];
        size_t kb = (size_t)s * 32 * H_DIM;
        #pragma unroll
        for (int p = 0; p < 2; p++) { lo[p] = *(const float4*)(bp[p] + kb);
                                      hi[p] = *(const float4*)(bp[p] + kb + 4); }
        stsB(s, lo, hi);
    }

    for (int s = 0; s < NS; s++) {
        float4 lo[2], hi[2];
        bool pre = (s + 3 < NS);
        if (pre) {
            size_t kb = (size_t)(s + 3) * 32 * H_DIM;
            #pragma unroll
            for (int p = 0; p < 2; p++) { lo[p] = *(const float4*)(bp[p] + kb);
                                          hi[p] = *(const float4*)(bp[p] + kb + 4); }
        }
        int w = NS - 1 - s;
        if (w >= 2) cp_wait2(); else if (w == 1) cp_wait1(); else cp_wait0();
        __syncthreads();
        uint32_t sbase = sb + SM_STAGE0 + (uint32_t)((s & 3) * STAGE_BYTES);
        #pragma unroll
        for (int kk = 0; kk < 2; kk++) {
            uint32_t a[4][4], b[2][4];
            #pragma unroll
            for (int mf = 0; mf < 4; mf++)
                ldsm_x4(a[mf][0], a[mf][1], a[mf][2], a[mf][3],
                        sbase + aoff[mf] + kk * 32);
            #pragma unroll
            for (int p = 0; p < 2; p++)
                ldsm_x4t(b[p][0], b[p][1], b[p][2], b[p][3],
                         sbase + boff[p] + kk * 16 * (B_PITCH * 2));
            #pragma unroll
            for (int mf = 0; mf < 4; mf++) {
                #pragma unroll
                for (int p = 0; p < 2; p++) {
                    mma16816(acc[mf][p * 2],     a[mf][0], a[mf][1], a[mf][2], a[mf][3],
                             b[p][0], b[p][1]);
                    mma16816(acc[mf][p * 2 + 1], a[mf][0], a[mf][1], a[mf][2], a[mf][3],
                             b[p][2], b[p][3]);
                }
            }
        }
        if (pre) { issueA(s + 3); stsB(s + 3, lo, hi); }
    }

    #pragma unroll
    for (int mf = 0; mf < 4; mf++) {
        int r0 = wm * 64 + mf * 16 + (lane >> 2);
        #pragma unroll
        for (int nf = 0; nf < 4; nf++) {
            int col = n0 + wn * 32 + nf * 8 + (lane & 3) * 2;
            if (r0 < mrem) {
                float2 v = { acc[mf][nf][0], acc[mf][nf][1] };
                *(float2*)(g_dout + (size_t)(rstart + r0) * H_DIM + col) = v;
            }
            if (r0 + 8 < mrem) {
                float2 v = { acc[mf][nf][2], acc[mf][nf][3] };
                *(float2*)(g_dout + (size_t)(rstart + r0 + 8) * H_DIM + col) = v;
            }
        }
    }
}

// ---------------- combine ----------------
__global__ void combine_kernel(float* __restrict__ out) {
    int t = blockIdx.x;
    int r0 = g_rowOf[t * K_TOP + 0], r1 = g_rowOf[t * K_TOP + 1];
    int r2 = g_rowOf[t * K_TOP + 2], r3 = g_rowOf[t * K_TOP + 3];
    float w0 = g_topk_w[t * K_TOP + 0], w1 = g_topk_w[t * K_TOP + 1];
    float w2 = g_topk_w[t * K_TOP + 2], w3 = g_topk_w[t * K_TOP + 3];
    const float4* d0 = (const float4*)(g_dout + (size_t)r0 * H_DIM);
    const float4* d1 = (const float4*)(g_dout + (size_t)r1 * H_DIM);
    const float4* d2 = (const float4*)(g_dout + (size_t)r2 * H_DIM);
    const float4* d3 = (const float4*)(g_dout + (size_t)r3 * H_DIM);
    float4* o = (float4*)(out + (size_t)t * H_DIM);
    for (int i = threadIdx.x; i < H_DIM / 4; i += 256) {
        float4 a = d0[i], b = d1[i], c = d2[i], d = d3[i];
        float4 r;
        r.x = w0 * a.x + w1 * b.x + w2 * c.x + w3 * d.x;
        r.y = w0 * a.y + w1 * b.y + w2 * c.y + w3 * d.y;
        r.z = w0 * a.z + w1 * b.z + w2 * c.z + w3 * d.z;
        r.w = w0 * a.w + w1 * b.w + w2 * c.w + w3 * d.w;
        o[i] = r;
    }
}

// ---------------- launch ----------------
extern "C" void kernel_launch(void* const* d_in, const int* in_sizes, int n_in,
                              void* d_out, int out_size) {
    const float* hidden = (const float*)d_in[0];
    const float* gate_w = (const float*)d_in[1];
    const float* w1     = (const float*)d_in[2];
    const float* w3     = (const float*)d_in[3];
    const float* w2     = (const float*)d_in[4];
    float* out = (float*)d_out;

    cudaFuncSetAttribute(gemm1_kernel, cudaFuncAttributeMaxDynamicSharedMemorySize, SM_BYTES);
    cudaFuncSetAttribute(gemm2_kernel, cudaFuncAttributeMaxDynamicSharedMemorySize, SM_BYTES);

    init_kernel<<<1, 32>>>();                                    // 1
    router_kernel<<<T_TOK / 4, 128>>>(hidden, gate_w);           // 2
    fill_kernel<<<E_NUM, 256>>>();                               // 3
    gemm1_kernel<<<dim3(I_DIM / 64, T_TOK / 128, E_NUM), 256, SM_BYTES>>>(w1, w3);  // 4
    gemm2_kernel<<<dim3(H_DIM / 128, T_TOK / 128, E_NUM), 256, SM_BYTES>>>(w2);     // 5
    combine_kernel<<<T_TOK, 256>>>(out);                         // 6
}

// round 8
// speedup vs baseline: 4.5991x; 1.0236x over previous
#include <cuda_runtime.h>
#include <cuda_fp16.h>
#include <cstdint>
#include <cstddef>

#define T_TOK 2048
#define H_DIM 2048
#define I_DIM 1024
#define E_NUM 16
#define K_TOP 4
#define NPAIR (T_TOK * K_TOP)

// ---------------- static device scratch ----------------
__device__ int    g_topk_idx[T_TOK * K_TOP];
__device__ float  g_topk_w[T_TOK * K_TOP];
__device__ int    g_counts[E_NUM];
__device__ int    g_off[E_NUM];
__device__ int    g_srcTok[NPAIR];
__device__ int    g_rowOf[T_TOK * K_TOP];
__device__ __half g_hh[(size_t)T_TOK * H_DIM];       // fp16 hidden [T, H]
__device__ __half g_act[(size_t)NPAIR * I_DIM];      // SwiGLU activations
__device__ float  g_dout[(size_t)NPAIR * H_DIM];     // per-pair down proj (unscaled)

// ---------------- helpers ----------------
__device__ __forceinline__ uint32_t smem_u32(const void* p) {
    return (uint32_t)__cvta_generic_to_shared(p);
}
__device__ __forceinline__ void cpa16(uint32_t s, const void* g) {
    asm volatile("cp.async.cg.shared.global [%0], [%1], 16;\n" :: "r"(s), "l"(g));
}
__device__ __forceinline__ void cp_commit() { asm volatile("cp.async.commit_group;\n"); }
__device__ __forceinline__ void cp_wait2()  { asm volatile("cp.async.wait_group 2;\n"); }
__device__ __forceinline__ void cp_wait1()  { asm volatile("cp.async.wait_group 1;\n"); }
__device__ __forceinline__ void cp_wait0()  { asm volatile("cp.async.wait_group 0;\n"); }

__device__ __forceinline__ void ldsm_x4(uint32_t& r0, uint32_t& r1, uint32_t& r2, uint32_t& r3,
                                        uint32_t addr) {
    asm volatile("ldmatrix.sync.aligned.m8n8.x4.shared.b16 {%0,%1,%2,%3}, [%4];"
                 : "=r"(r0), "=r"(r1), "=r"(r2), "=r"(r3) : "r"(addr));
}
__device__ __forceinline__ void ldsm_x4t(uint32_t& r0, uint32_t& r1, uint32_t& r2, uint32_t& r3,
                                         uint32_t addr) {
    asm volatile("ldmatrix.sync.aligned.m8n8.x4.trans.shared.b16 {%0,%1,%2,%3}, [%4];"
                 : "=r"(r0), "=r"(r1), "=r"(r2), "=r"(r3) : "r"(addr));
}
__device__ __forceinline__ void mma16816(float* d, uint32_t a0, uint32_t a1, uint32_t a2,
                                         uint32_t a3, uint32_t b0, uint32_t b1) {
    asm volatile(
        "mma.sync.aligned.m16n8k16.row.col.f32.f16.f16.f32 "
        "{%0,%1,%2,%3}, {%4,%5,%6,%7}, {%8,%9}, {%0,%1,%2,%3};"
        : "+f"(d[0]), "+f"(d[1]), "+f"(d[2]), "+f"(d[3])
        : "r"(a0), "r"(a1), "r"(a2), "r"(a3), "r"(b0), "r"(b1));
}
__device__ __forceinline__ uint4 pack8_interleave(float4 a, float4 b) {
    __half2 h0 = __floats2half2_rn(a.x, b.x);
    __half2 h1 = __floats2half2_rn(a.y, b.y);
    __half2 h2 = __floats2half2_rn(a.z, b.z);
    __half2 h3 = __floats2half2_rn(a.w, b.w);
    uint4 o;
    o.x = *(uint32_t*)&h0; o.y = *(uint32_t*)&h1;
    o.z = *(uint32_t*)&h2; o.w = *(uint32_t*)&h3;
    return o;
}
__device__ __forceinline__ uint4 pack8_linear(float4 a, float4 b) {
    __half2 h0 = __floats2half2_rn(a.x, a.y);
    __half2 h1 = __floats2half2_rn(a.z, a.w);
    __half2 h2 = __floats2half2_rn(b.x, b.y);
    __half2 h3 = __floats2half2_rn(b.z, b.w);
    uint4 o;
    o.x = *(uint32_t*)&h0; o.y = *(uint32_t*)&h1;
    o.z = *(uint32_t*)&h2; o.w = *(uint32_t*)&h3;
    return o;
}

// ---------------- init ----------------
__global__ void init_kernel() {
    if (threadIdx.x < E_NUM) g_counts[threadIdx.x] = 0;
}

// ---------------- router: warp per token ----------------
__global__ __launch_bounds__(128) void router_kernel(const float* __restrict__ hidden,
                                                     const float* __restrict__ gate_w) {
    int warp = threadIdx.x >> 5, lane = threadIdx.x & 31;
    int t = blockIdx.x * 4 + warp;
    const float4* hrow = (const float4*)(hidden + (size_t)t * H_DIM);
    __half2* hh = (__half2*)(g_hh + (size_t)t * H_DIM);
    float acc[E_NUM];
    #pragma unroll
    for (int e = 0; e < E_NUM; e++) acc[e] = 0.f;

    #pragma unroll 4
    for (int i = 0; i < 16; i++) {
        int idx = i * 32 + lane;
        float4 h = hrow[idx];
        hh[idx * 2]     = __floats2half2_rn(h.x, h.y);
        hh[idx * 2 + 1] = __floats2half2_rn(h.z, h.w);
        #pragma unroll
        for (int e = 0; e < E_NUM; e++) {
            float4 g = ((const float4*)(gate_w + (size_t)e * H_DIM))[idx];
            acc[e] += h.x * g.x + h.y * g.y + h.z * g.z + h.w * g.w;
        }
    }
    #pragma unroll
    for (int e = 0; e < E_NUM; e++)
        #pragma unroll
        for (int o = 16; o > 0; o >>= 1)
            acc[e] += __shfl_xor_sync(0xffffffffu, acc[e], o);

    if (lane == 0) {
        float mx = -1e30f;
        #pragma unroll
        for (int e = 0; e < E_NUM; e++) mx = fmaxf(mx, acc[e]);
        float pr[E_NUM];
        #pragma unroll
        for (int e = 0; e < E_NUM; e++) pr[e] = __expf(acc[e] - mx);
        int idx[K_TOP]; float w[K_TOP];
        #pragma unroll
        for (int k = 0; k < K_TOP; k++) {
            float bv = -1.f; int bi = 0;
            #pragma unroll
            for (int e = 0; e < E_NUM; e++) {
                bool used = false;
                for (int kk = 0; kk < k; kk++) if (idx[kk] == e) used = true;
                if (!used && pr[e] > bv) { bv = pr[e]; bi = e; }
            }
            idx[k] = bi; w[k] = bv;
        }
        float inv = 1.f / (w[0] + w[1] + w[2] + w[3]);
        #pragma unroll
        for (int k = 0; k < K_TOP; k++) {
            g_topk_idx[t * K_TOP + k] = idx[k];
            g_topk_w[t * K_TOP + k]   = w[k] * inv;
            atomicAdd(&g_counts[idx[k]], 1);
        }
    }
}

// ---------------- fill (prefix inlined) ----------------
__global__ void fill_kernel() {
    int e = blockIdx.x;
    int start = 0;
    for (int i = 0; i < e; i++) start += g_counts[i];
    __shared__ int s_counter, s_prefix[8], s_wsum[8];
    int tid = threadIdx.x, lane = tid & 31, wid = tid >> 5;
    if (tid == 0) { g_off[e] = start; s_counter = 0; }
    __syncthreads();
    for (int base = 0; base < T_TOK; base += 256) {
        int t = base + tid;
        int myk = -1;
        #pragma unroll
        for (int k = 0; k < K_TOP; k++) if (g_topk_idx[t * K_TOP + k] == e) myk = k;
        unsigned bal = __ballot_sync(0xffffffffu, myk >= 0);
        if (lane == 0) s_wsum[wid] = __popc(bal);
        __syncthreads();
        if (tid == 0) {
            int acc = s_counter;
            for (int w = 0; w < 8; w++) { s_prefix[w] = acc; acc += s_wsum[w]; }
            s_counter = acc;
        }
        __syncthreads();
        if (myk >= 0) {
            int j = s_prefix[wid] + __popc(bal & ((1u << lane) - 1));
            int r = start + j;
            g_srcTok[r] = t;
            g_rowOf[t * K_TOP + myk] = r;
        }
        __syncthreads();
    }
}

// ---------------- GEMM smem layout: 4-stage ring ----------------
#define A_PITCH 40
#define B_PITCH 136
#define A_BYTES (128 * A_PITCH * 2)
#define STAGE_BYTES (A_BYTES + 32 * B_PITCH * 2)
#define SM_STAGE0 1024
#define N_STAGES 4
#define SM_BYTES (SM_STAGE0 + N_STAGES * STAGE_BYTES)

// ---------------- GEMM1: 128 threads, 4 warps of 64x64; B = fused-convert fp32 w1/w3 --------
__global__ __launch_bounds__(128, 2) void gemm1_kernel(const float* __restrict__ w1,
                                                       const float* __restrict__ w3) {
    int e = blockIdx.z;
    int M_e = g_counts[e];
    int mbase = blockIdx.y * 128;
    if (mbase >= M_e) return;
    int n0o = blockIdx.x * 64;                 // 64 I-cols -> 128 interleaved B cols
    int rstart = g_off[e] + mbase;
    int mrem = M_e - mbase; if (mrem > 128) mrem = 128;

    extern __shared__ __align__(16) char smem[];
    int* rows_s = (int*)smem;
    uint32_t sb = smem_u32(smem);
    int tid = threadIdx.x, lane = tid & 31;
    int warp = tid >> 5, wm = warp >> 1, wn = warp & 1;   // 2 x 2 warps, warp tile 64x64

    rows_s[tid] = (tid < mrem) ? g_srcTok[rstart + tid] : 0;
    __syncthreads();

    // A cp.async: 4 chunks per thread (rows m, m+32, m+64, m+96)
    int am = tid >> 2, aseg = tid & 3;
    const __half* asrc[4]; uint32_t adst[4];
    #pragma unroll
    for (int p = 0; p < 4; p++) {
        int m = am + p * 32;
        asrc[p] = g_hh + (size_t)rows_s[m] * H_DIM + aseg * 8;
        adst[p] = sb + SM_STAGE0 + m * (A_PITCH * 2) + aseg * 16;
    }

    // B fp32 slots: 4 per thread; slot -> (k, i4)
    const float* b1p[4]; const float* b3p[4]; uint32_t bofs[4];
    #pragma unroll
    for (int p = 0; p < 4; p++) {
        int slot = tid + p * 128;
        int k = slot >> 4, i4 = slot & 15;
        size_t o = ((size_t)e * H_DIM + k) * I_DIM + n0o + i4 * 4;
        b1p[p] = w1 + o;
        b3p[p] = w3 + o;
        bofs[p] = A_BYTES + (uint32_t)(k * (B_PITCH * 2) + i4 * 16);
    }

    uint32_t aoff[4], boff[4];
    #pragma unroll
    for (int mf = 0; mf < 4; mf++)
        aoff[mf] = (wm * 64 + mf * 16 + (lane & 15)) * (A_PITCH * 2) + (lane >> 4) * 16;
    #pragma unroll
    for (int p = 0; p < 4; p++)
        boff[p] = A_BYTES + ((lane & 7) + 8 * ((lane >> 3) & 1)) * (B_PITCH * 2)
                + (wn * 64 + p * 16 + 8 * (lane >> 4)) * 2;

    float acc[4][8][4];
    #pragma unroll
    for (int i = 0; i < 4; i++)
        #pragma unroll
        for (int j = 0; j < 8; j++)
            #pragma unroll
            for (int r = 0; r < 4; r++) acc[i][j][r] = 0.f;

    auto issueA = [&](int s) {
        uint32_t so = (uint32_t)((s & 3) * STAGE_BYTES);
        size_t ka = (size_t)s * 32;
        #pragma unroll
        for (int p = 0; p < 4; p++) cpa16(adst[p] + so, asrc[p] + ka);
        cp_commit();
    };
    auto stsB = [&](int s, const float4* f1, const float4* f3) {
        uint32_t so = (uint32_t)((s & 3) * STAGE_BYTES);
        #pragma unroll
        for (int p = 0; p < 4; p++)
            *(uint4*)(smem + SM_STAGE0 + so + bofs[p]) = pack8_interleave(f1[p], f3[p]);
    };

    const int NS = H_DIM / 32;   // 64
    issueA(0); issueA(1); issueA(2);
    #pragma unroll
    for (int s = 0; s < 3; s++) {
        float4 f1[4], f3[4];
        size_t kb = (size_t)s * 32 * I_DIM;
        #pragma unroll
        for (int p = 0; p < 4; p++) { f1[p] = *(const float4*)(b1p[p] + kb);
                                      f3[p] = *(const float4*)(b3p[p] + kb); }
        stsB(s, f1, f3);
    }

    for (int s = 0; s < NS; s++) {
        float4 f1[4], f3[4];
        bool pre = (s + 3 < NS);
        if (pre) {
            size_t kb = (size_t)(s + 3) * 32 * I_DIM;
            #pragma unroll
            for (int p = 0; p < 4; p++) { f1[p] = *(const float4*)(b1p[p] + kb);
                                          f3[p] = *(const float4*)(b3p[p] + kb); }
        }
        int w = NS - 1 - s;
        if (w >= 2) cp_wait2(); else if (w == 1) cp_wait1(); else cp_wait0();
        __syncthreads();
        uint32_t sbase = sb + SM_STAGE0 + (uint32_t)((s & 3) * STAGE_BYTES);
        #pragma unroll
        for (int kk = 0; kk < 2; kk++) {
            uint32_t a[4][4], b[4][4];
            #pragma unroll
            for (int mf = 0; mf < 4; mf++)
                ldsm_x4(a[mf][0], a[mf][1], a[mf][2], a[mf][3],
                        sbase + aoff[mf] + kk * 32);
            #pragma unroll
            for (int p = 0; p < 4; p++)
                ldsm_x4t(b[p][0], b[p][1], b[p][2], b[p][3],
                         sbase + boff[p] + kk * 16 * (B_PITCH * 2));
            #pragma unroll
            for (int mf = 0; mf < 4; mf++) {
                #pragma unroll
                for (int p = 0; p < 4; p++) {
                    mma16816(acc[mf][p * 2],     a[mf][0], a[mf][1], a[mf][2], a[mf][3],
                             b[p][0], b[p][1]);
                    mma16816(acc[mf][p * 2 + 1], a[mf][0], a[mf][1], a[mf][2], a[mf][3],
                             b[p][2], b[p][3]);
                }
            }
        }
        if (pre) { issueA(s + 3); stsB(s + 3, f1, f3); }
    }

    // epilogue: c0=w1, c1=w3 pairs -> silu(c0)*c1
    #pragma unroll
    for (int mf = 0; mf < 4; mf++) {
        int r0 = wm * 64 + mf * 16 + (lane >> 2);
        #pragma unroll
        for (int nf = 0; nf < 8; nf++) {
            int col = n0o + wn * 32 + nf * 4 + (lane & 3);
            float x0 = acc[mf][nf][0], y0 = acc[mf][nf][1];
            float x1 = acc[mf][nf][2], y1 = acc[mf][nf][3];
            float v0 = x0 / (1.0f + __expf(-x0)) * y0;
            float v1 = x1 / (1.0f + __expf(-x1)) * y1;
            if (r0 < mrem)     g_act[(size_t)(rstart + r0) * I_DIM + col]     = __float2half(v0);
            if (r0 + 8 < mrem) g_act[(size_t)(rstart + r0 + 8) * I_DIM + col] = __float2half(v1);
        }
    }
}

// ---------------- GEMM2: 128 threads, 4 warps of 64x64; B = fused fp32 w2 ----------------
__global__ __launch_bounds__(128, 2) void gemm2_kernel(const float* __restrict__ w2) {
    int e = blockIdx.z;
    int M_e = g_counts[e];
    int mbase = blockIdx.y * 128;
    if (mbase >= M_e) return;
    int n0 = blockIdx.x * 128;
    int rstart = g_off[e] + mbase;
    int mrem = M_e - mbase; if (mrem > 128) mrem = 128;

    extern __shared__ __align__(16) char smem[];
    uint32_t sb = smem_u32(smem);
    int tid = threadIdx.x, lane = tid & 31;
    int warp = tid >> 5, wm = warp >> 1, wn = warp & 1;

    int am = tid >> 2, aseg = tid & 3;
    const __half* asrc[4]; uint32_t adst[4];
    #pragma unroll
    for (int p = 0; p < 4; p++) {
        int m = am + p * 32;
        int ar = rstart + m; if (ar >= NPAIR) ar = NPAIR - 1;
        asrc[p] = g_act + (size_t)ar * I_DIM + aseg * 8;
        adst[p] = sb + SM_STAGE0 + m * (A_PITCH * 2) + aseg * 16;
    }

    const float* bp[4]; uint32_t bofs[4];
    #pragma unroll
    for (int p = 0; p < 4; p++) {
        int slot = tid + p * 128;
        int k = slot >> 4, n8 = slot & 15;
        bp[p] = w2 + ((size_t)e * I_DIM + k) * H_DIM + n0 + n8 * 8;
        bofs[p] = A_BYTES + (uint32_t)(k * (B_PITCH * 2) + n8 * 16);
    }

    uint32_t aoff[4], boff[4];
    #pragma unroll
    for (int mf = 0; mf < 4; mf++)
        aoff[mf] = (wm * 64 + mf * 16 + (lane & 15)) * (A_PITCH * 2) + (lane >> 4) * 16;
    #pragma unroll
    for (int p = 0; p < 4; p++)
        boff[p] = A_BYTES + ((lane & 7) + 8 * ((lane >> 3) & 1)) * (B_PITCH * 2)
                + (wn * 64 + p * 16 + 8 * (lane >> 4)) * 2;

    float acc[4][8][4];
    #pragma unroll
    for (int i = 0; i < 4; i++)
        #pragma unroll
        for (int j = 0; j < 8; j++)
            #pragma unroll
            for (int r = 0; r < 4; r++) acc[i][j][r] = 0.f;

    auto issueA = [&](int s) {
        uint32_t so = (uint32_t)((s & 3) * STAGE_BYTES);
        size_t ka = (size_t)s * 32;
        #pragma unroll
        for (int p = 0; p < 4; p++) cpa16(adst[p] + so, asrc[p] + ka);
        cp_commit();
    };
    auto stsB = [&](int s, const float4* lo, const float4* hi) {
        uint32_t so = (uint32_t)((s & 3) * STAGE_BYTES);
        #pragma unroll
        for (int p = 0; p < 4; p++)
            *(uint4*)(smem + SM_STAGE0 + so + bofs[p]) = pack8_linear(lo[p], hi[p]);
    };

    const int NS = I_DIM / 32;   // 32
    issueA(0); issueA(1); issueA(2);
    #pragma unroll
    for (int s = 0; s < 3; s++) {
        float4 lo[4], hi[4];
        size_t kb = (size_t)s * 32 * H_DIM;
        #pragma unroll
        for (int p = 0; p < 4; p++) { lo[p] = *(const float4*)(bp[p] + kb);
                                      hi[p] = *(const float4*)(bp[p] + kb + 4); }
        stsB(s, lo, hi);
    }

    for (int s = 0; s < NS; s++) {
        float4 lo[4], hi[4];
        bool pre = (s + 3 < NS);
        if (pre) {
            size_t kb = (size_t)(s + 3) * 32 * H_DIM;
            #pragma unroll
            for (int p = 0; p < 4; p++) { lo[p] = *(const float4*)(bp[p] + kb);
                                          hi[p] = *(const float4*)(bp[p] + kb + 4); }
        }
        int w = NS - 1 - s;
        if (w >= 2) cp_wait2(); else if (w == 1) cp_wait1(); else cp_wait0();
        __syncthreads();
        uint32_t sbase = sb + SM_STAGE0 + (uint32_t)((s & 3) * STAGE_BYTES);
        #pragma unroll
        for (int kk = 0; kk < 2; kk++) {
            uint32_t a[4][4], b[4][4];
            #pragma unroll
            for (int mf = 0; mf < 4; mf++)
                ldsm_x4(a[mf][0], a[mf][1], a[mf][2], a[mf][3],
                        sbase + aoff[mf] + kk * 32);
            #pragma unroll
            for (int p = 0; p < 4; p++)
                ldsm_x4t(b[p][0], b[p][1], b[p][2], b[p][3],
                         sbase + boff[p] + kk * 16 * (B_PITCH * 2));
            #pragma unroll
            for (int mf = 0; mf < 4; mf++) {
                #pragma unroll
                for (int p = 0; p < 4; p++) {
                    mma16816(acc[mf][p * 2],     a[mf][0], a[mf][1], a[mf][2], a[mf][3],
                             b[p][0], b[p][1]);
                    mma16816(acc[mf][p * 2 + 1], a[mf][0], a[mf][1], a[mf][2], a[mf][3],
                             b[p][2], b[p][3]);
                }
            }
        }
        if (pre) { issueA(s + 3); stsB(s + 3, lo, hi); }
    }

    #pragma unroll
    for (int mf = 0; mf < 4; mf++) {
        int r0 = wm * 64 + mf * 16 + (lane >> 2);
        #pragma unroll
        for (int nf = 0; nf < 8; nf++) {
            int col = n0 + wn * 64 + nf * 8 + (lane & 3) * 2;
            if (r0 < mrem) {
                float2 v = { acc[mf][nf][0], acc[mf][nf][1] };
                *(float2*)(g_dout + (size_t)(rstart + r0) * H_DIM + col) = v;
            }
            if (r0 + 8 < mrem) {
                float2 v = { acc[mf][nf][2], acc[mf][nf][3] };
                *(float2*)(g_dout + (size_t)(rstart + r0 + 8) * H_DIM + col) = v;
            }
        }
    }
}

// ---------------- combine ----------------
__global__ void combine_kernel(float* __restrict__ out) {
    int t = blockIdx.x;
    int r0 = g_rowOf[t * K_TOP + 0], r1 = g_rowOf[t * K_TOP + 1];
    int r2 = g_rowOf[t * K_TOP + 2], r3 = g_rowOf[t * K_TOP + 3];
    float w0 = g_topk_w[t * K_TOP + 0], w1 = g_topk_w[t * K_TOP + 1];
    float w2 = g_topk_w[t * K_TOP + 2], w3 = g_topk_w[t * K_TOP + 3];
    const float4* d0 = (const float4*)(g_dout + (size_t)r0 * H_DIM);
    const float4* d1 = (const float4*)(g_dout + (size_t)r1 * H_DIM);
    const float4* d2 = (const float4*)(g_dout + (size_t)r2 * H_DIM);
    const float4* d3 = (const float4*)(g_dout + (size_t)r3 * H_DIM);
    float4* o = (float4*)(out + (size_t)t * H_DIM);
    for (int i = threadIdx.x; i < H_DIM / 4; i += 256) {
        float4 a = d0[i], b = d1[i], c = d2[i], d = d3[i];
        float4 r;
        r.x = w0 * a.x + w1 * b.x + w2 * c.x + w3 * d.x;
        r.y = w0 * a.y + w1 * b.y + w2 * c.y + w3 * d.y;
        r.z = w0 * a.z + w1 * b.z + w2 * c.z + w3 * d.z;
        r.w = w0 * a.w + w1 * b.w + w2 * c.w + w3 * d.w;
        o[i] = r;
    }
}

// ---------------- launch ----------------
extern "C" void kernel_launch(void* const* d_in, const int* in_sizes, int n_in,
                              void* d_out, int out_size) {
    const float* hidden = (const float*)d_in[0];
    const float* gate_w = (const float*)d_in[1];
    const float* w1     = (const float*)d_in[2];
    const float* w3     = (const float*)d_in[3];
    const float* w2     = (const float*)d_in[4];
    float* out = (float*)d_out;

    cudaFuncSetAttribute(gemm1_kernel, cudaFuncAttributeMaxDynamicSharedMemorySize, SM_BYTES);
    cudaFuncSetAttribute(gemm2_kernel, cudaFuncAttributeMaxDynamicSharedMemorySize, SM_BYTES);

    init_kernel<<<1, 32>>>();                                    // 1
    router_kernel<<<T_TOK / 4, 128>>>(hidden, gate_w);           // 2
    fill_kernel<<<E_NUM, 256>>>();                               // 3
    gemm1_kernel<<<dim3(I_DIM / 64, T_TOK / 128, E_NUM), 128, SM_BYTES>>>(w1, w3);  // 4
    gemm2_kernel<<<dim3(H_DIM / 128, T_TOK / 128, E_NUM), 128, SM_BYTES>>>(w2);     // 5
    combine_kernel<<<T_TOK, 256>>>(out);                         // 6
}